// round 2
// baseline (speedup 1.0000x reference)
#include <cuda_runtime.h>
#include <math.h>
#include <float.h>

// Problem dims (fixed)
#define BATCH 2
#define SEQ   2048
#define DMODEL 1024
#define NHEAD 16
#define HDIM  64
#define FFN   4096
#define MTOK  (BATCH*SEQ)          // 4096 token rows

// ---------------- scratch (allocation-free: __device__ globals) ----------------
__device__ float g_ln1 [MTOK*DMODEL];
__device__ float g_q   [MTOK*DMODEL];
__device__ float g_k   [MTOK*DMODEL];
__device__ float g_v   [MTOK*DMODEL];
__device__ float g_ctx [MTOK*DMODEL];
__device__ float g_res1[MTOK*DMODEL];
__device__ float g_ln2 [MTOK*DMODEL];
__device__ float g_ffn [MTOK*FFN];

// ---------------- helpers ----------------
__device__ __forceinline__ float gelu_tanh(float x) {
    const float c = 0.7978845608028654f; // sqrt(2/pi)
    float t = c * (x + 0.044715f * x * x * x);
    return 0.5f * x * (1.0f + tanhf(t));
}

// ---------------- LayerNorm (torch var: ddof=1) ----------------
// one block per row of 1024, 256 threads, 4 elems/thread
__global__ __launch_bounds__(256)
void ln_kernel(const float* __restrict__ x, const float* __restrict__ sc,
               const float* __restrict__ sh, float* __restrict__ out)
{
    int row = blockIdx.x;
    int tid = threadIdx.x;
    const float4 a = *(const float4*)&x[(size_t)row * DMODEL + tid * 4];

    float s = a.x + a.y + a.z + a.w;
    float q = a.x*a.x + a.y*a.y + a.z*a.z + a.w*a.w;
    #pragma unroll
    for (int off = 16; off > 0; off >>= 1) {
        s += __shfl_xor_sync(0xFFFFFFFFu, s, off);
        q += __shfl_xor_sync(0xFFFFFFFFu, q, off);
    }
    __shared__ float reds[8], redq[8], stats[2];
    int wid = tid >> 5, lane = tid & 31;
    if (lane == 0) { reds[wid] = s; redq[wid] = q; }
    __syncthreads();
    if (tid == 0) {
        float S = 0.f, Q = 0.f;
        #pragma unroll
        for (int i = 0; i < 8; i++) { S += reds[i]; Q += redq[i]; }
        float mean = S * (1.0f / DMODEL);
        float var  = (Q - S * mean) * (1.0f / (DMODEL - 1)); // ddof=1
        stats[0] = mean;
        stats[1] = rsqrtf(var + 1e-5f);
    }
    __syncthreads();
    float mean = stats[0], rstd = stats[1];
    const float4 scv = *(const float4*)&sc[tid * 4];
    const float4 shv = *(const float4*)&sh[tid * 4];
    float4 o;
    o.x = (a.x - mean) * rstd * scv.x + shv.x;
    o.y = (a.y - mean) * rstd * scv.y + shv.y;
    o.z = (a.z - mean) * rstd * scv.z + shv.z;
    o.w = (a.w - mean) * rstd * scv.w + shv.w;
    *(float4*)&out[(size_t)row * DMODEL + tid * 4] = o;
}

// ---------------- GEMM: C[M,N] = A[M,K] @ B[K,N]  (+epilogues) ----------------
// BM=BN=128, BK=16, 256 threads, 8x8 microtile with split mapping:
// thread (tx,ty) owns rows {ty*4..+3, 64+ty*4..+3}, cols {tx*4..+3, 64+tx*4..+3}
// EPI: 0=none, 1=+bias, 2=+bias,gelu, 3=+bias,+res
template<int EPI>
__global__ __launch_bounds__(256)
void gemm128(const float* __restrict__ A, const float* __restrict__ B,
             const float* __restrict__ bias, const float* __restrict__ res,
             float* __restrict__ C, int M, int N, int K)
{
    __shared__ float As[16][128];
    __shared__ float Bs[16][128];

    const int tid = threadIdx.x;
    const int tx = tid & 15;
    const int ty = tid >> 4;
    const int row0 = blockIdx.y * 128;
    const int col0 = blockIdx.x * 128;

    float acc[8][8];
    #pragma unroll
    for (int i = 0; i < 8; i++)
        #pragma unroll
        for (int j = 0; j < 8; j++) acc[i][j] = 0.f;

    for (int k0 = 0; k0 < K; k0 += 16) {
        // load A tile 128x16 (transposed into As), B tile 16x128
        #pragma unroll
        for (int it = 0; it < 2; it++) {
            int idx = tid + it * 256;           // 0..511
            int arow = idx >> 2;                // 0..127
            int acol = (idx & 3) * 4;           // 0,4,8,12
            float4 a = *(const float4*)&A[(size_t)(row0 + arow) * K + k0 + acol];
            As[acol + 0][arow] = a.x;
            As[acol + 1][arow] = a.y;
            As[acol + 2][arow] = a.z;
            As[acol + 3][arow] = a.w;
            int brow = idx >> 5;                // 0..15
            int bcol = (idx & 31) * 4;          // 0..124
            *(float4*)&Bs[brow][bcol] =
                *(const float4*)&B[(size_t)(k0 + brow) * N + col0 + bcol];
        }
        __syncthreads();

        #pragma unroll
        for (int kk = 0; kk < 16; kk++) {
            float ra[8], rb[8];
            *(float4*)&ra[0] = *(const float4*)&As[kk][ty * 4];
            *(float4*)&ra[4] = *(const float4*)&As[kk][64 + ty * 4];
            *(float4*)&rb[0] = *(const float4*)&Bs[kk][tx * 4];
            *(float4*)&rb[4] = *(const float4*)&Bs[kk][64 + tx * 4];
            #pragma unroll
            for (int i = 0; i < 8; i++)
                #pragma unroll
                for (int j = 0; j < 8; j++)
                    acc[i][j] += ra[i] * rb[j];
        }
        __syncthreads();
    }

    // epilogue
    #pragma unroll
    for (int i = 0; i < 8; i++) {
        int gr = row0 + ((i < 4) ? (ty * 4 + i) : (64 + ty * 4 + i - 4));
        #pragma unroll
        for (int jh = 0; jh < 2; jh++) {
            int gc = col0 + ((jh == 0) ? (tx * 4) : (64 + tx * 4));
            int jb = jh * 4;
            float4 c;
            c.x = acc[i][jb + 0]; c.y = acc[i][jb + 1];
            c.z = acc[i][jb + 2]; c.w = acc[i][jb + 3];
            if (EPI >= 1) {
                const float4 bv = *(const float4*)&bias[gc];
                c.x += bv.x; c.y += bv.y; c.z += bv.z; c.w += bv.w;
            }
            if (EPI == 2) {
                c.x = gelu_tanh(c.x); c.y = gelu_tanh(c.y);
                c.z = gelu_tanh(c.z); c.w = gelu_tanh(c.w);
            }
            if (EPI == 3) {
                const float4 rv = *(const float4*)&res[(size_t)gr * N + gc];
                c.x += rv.x; c.y += rv.y; c.z += rv.z; c.w += rv.w;
            }
            *(float4*)&C[(size_t)gr * N + gc] = c;
        }
    }
}

// ---------------- Flash attention (fp32, causal) ----------------
// grid: (S/64, B*H), 128 threads. Thread t owns query row t/2, dims half*32..+32.
// smem: Qs, Ks, Vs, Ss each 64x64 f32 = 64 KB dynamic.
__global__ __launch_bounds__(128)
void attn_kernel(const float* __restrict__ q, const float* __restrict__ k,
                 const float* __restrict__ v, float* __restrict__ ctx)
{
    extern __shared__ float sm[];
    float* Qs = sm;
    float* Ks = sm + 4096;
    float* Vs = sm + 8192;
    float* Ss = sm + 12288;

    const int bh = blockIdx.y;
    const int b = bh >> 4;
    const int h = bh & 15;
    const int m0 = blockIdx.x * 64;
    const int tid = threadIdx.x;
    const int r = tid >> 1;
    const int half = tid & 1;
    const int dbase = half * 32;
    const float scale = 0.125f; // 1/sqrt(64)
    const int gm = m0 + r;
    const size_t headoff = (size_t)h * HDIM;

    // load Q tile (64 rows x 64 cols)
    for (int i = tid; i < 1024; i += 128) {
        int rr = i >> 4, cc = (i & 15) * 4;
        *(float4*)&Qs[rr * 64 + cc] =
            *(const float4*)&q[((size_t)(b * SEQ + m0 + rr)) * DMODEL + headoff + cc];
    }
    __syncthreads();

    float4 qf[16];
    #pragma unroll
    for (int i = 0; i < 16; i++) qf[i] = *(const float4*)&Qs[r * 64 + i * 4];

    float acc[32];
    #pragma unroll
    for (int d = 0; d < 32; d++) acc[d] = 0.f;
    float mi = -INFINITY, li = 0.f;

    for (int n0 = 0; n0 <= m0; n0 += 64) {
        __syncthreads(); // protect Ks/Vs/Ss reuse
        for (int i = tid; i < 1024; i += 128) {
            int rr = i >> 4, cc = (i & 15) * 4;
            size_t g = ((size_t)(b * SEQ + n0 + rr)) * DMODEL + headoff + cc;
            *(float4*)&Ks[rr * 64 + cc] = *(const float4*)&k[g];
            *(float4*)&Vs[rr * 64 + cc] = *(const float4*)&v[g];
        }
        __syncthreads();

        // scores for my row r, cols [dbase, dbase+32)
        for (int n = dbase; n < dbase + 32; n++) {
            float s0 = 0.f, s1 = 0.f, s2 = 0.f, s3 = 0.f;
            #pragma unroll
            for (int i = 0; i < 16; i++) {
                float4 kf = *(const float4*)&Ks[n * 64 + i * 4];
                s0 += qf[i].x * kf.x; s1 += qf[i].y * kf.y;
                s2 += qf[i].z * kf.z; s3 += qf[i].w * kf.w;
            }
            float sv = (s0 + s1) + (s2 + s3);
            int gn = n0 + n;
            Ss[r * 64 + n] = (gn > gm) ? -INFINITY : sv * scale;
        }
        __syncthreads();

        // online softmax + V accumulate over full 64-wide score row
        float mt = -INFINITY;
        #pragma unroll
        for (int n = 0; n < 64; n++) mt = fmaxf(mt, Ss[r * 64 + n]);
        float mnew = fmaxf(mi, mt);
        float alpha = __expf(mi - mnew); // mi=-inf first iter -> 0
        li *= alpha;
        #pragma unroll
        for (int d = 0; d < 32; d++) acc[d] *= alpha;

        for (int n = 0; n < 64; n++) {
            float p = __expf(Ss[r * 64 + n] - mnew);
            li += p;
            #pragma unroll
            for (int i = 0; i < 8; i++) {
                float4 vf = *(const float4*)&Vs[n * 64 + dbase + i * 4];
                acc[i * 4 + 0] += p * vf.x;
                acc[i * 4 + 1] += p * vf.y;
                acc[i * 4 + 2] += p * vf.z;
                acc[i * 4 + 3] += p * vf.w;
            }
        }
        mi = mnew;
    }

    float inv = 1.0f / li;
    #pragma unroll
    for (int i = 0; i < 8; i++) {
        float4 o;
        o.x = acc[i * 4 + 0] * inv; o.y = acc[i * 4 + 1] * inv;
        o.z = acc[i * 4 + 2] * inv; o.w = acc[i * 4 + 3] * inv;
        *(float4*)&ctx[((size_t)(b * SEQ + gm)) * DMODEL + headoff + dbase + i * 4] = o;
    }
}

// ---------------- launch ----------------
extern "C" void kernel_launch(void* const* d_in, const int* in_sizes, int n_in,
                              void* d_out, int out_size)
{
    const float* x         = (const float*)d_in[0];
    const float* ln1_scale = (const float*)d_in[1];
    const float* ln1_shift = (const float*)d_in[2];
    const float* wq        = (const float*)d_in[3];
    const float* wk        = (const float*)d_in[4];
    const float* wv        = (const float*)d_in[5];
    const float* w_out     = (const float*)d_in[6];
    const float* b_out     = (const float*)d_in[7];
    const float* ln2_scale = (const float*)d_in[8];
    const float* ln2_shift = (const float*)d_in[9];
    const float* w1        = (const float*)d_in[10];
    const float* b1        = (const float*)d_in[11];
    const float* w2        = (const float*)d_in[12];
    const float* b2        = (const float*)d_in[13];
    float* out = (float*)d_out;

    float *p_ln1, *p_q, *p_k, *p_v, *p_ctx, *p_res1, *p_ln2, *p_ffn;
    cudaGetSymbolAddress((void**)&p_ln1,  g_ln1);
    cudaGetSymbolAddress((void**)&p_q,    g_q);
    cudaGetSymbolAddress((void**)&p_k,    g_k);
    cudaGetSymbolAddress((void**)&p_v,    g_v);
    cudaGetSymbolAddress((void**)&p_ctx,  g_ctx);
    cudaGetSymbolAddress((void**)&p_res1, g_res1);
    cudaGetSymbolAddress((void**)&p_ln2,  g_ln2);
    cudaGetSymbolAddress((void**)&p_ffn,  g_ffn);

    static bool attr_set = false;
    if (!attr_set) {
        cudaFuncSetAttribute(attn_kernel, cudaFuncAttributeMaxDynamicSharedMemorySize, 65536);
        attr_set = true;
    }

    dim3 gN1024(DMODEL / 128, MTOK / 128);  // (8, 32)
    dim3 gN4096(FFN / 128, MTOK / 128);     // (32, 32)

    // 1) LN1
    ln_kernel<<<MTOK, 256>>>(x, ln1_scale, ln1_shift, p_ln1);

    // 2) Q/K/V projections
    gemm128<0><<<gN1024, 256>>>(p_ln1, wq, nullptr, nullptr, p_q, MTOK, DMODEL, DMODEL);
    gemm128<0><<<gN1024, 256>>>(p_ln1, wk, nullptr, nullptr, p_k, MTOK, DMODEL, DMODEL);
    gemm128<0><<<gN1024, 256>>>(p_ln1, wv, nullptr, nullptr, p_v, MTOK, DMODEL, DMODEL);

    // 3) attention
    dim3 gAttn(SEQ / 64, BATCH * NHEAD);    // (32, 32)
    attn_kernel<<<gAttn, 128, 65536>>>(p_q, p_k, p_v, p_ctx);

    // 4) out projection + bias + residual(x)
    gemm128<3><<<gN1024, 256>>>(p_ctx, w_out, b_out, x, p_res1, MTOK, DMODEL, DMODEL);

    // 5) LN2
    ln_kernel<<<MTOK, 256>>>(p_res1, ln2_scale, ln2_shift, p_ln2);

    // 6) FFN1 + bias + gelu
    gemm128<2><<<gN4096, 256>>>(p_ln2, w1, b1, nullptr, p_ffn, MTOK, FFN, DMODEL);

    // 7) FFN2 + bias + residual(res1) -> out
    gemm128<3><<<gN1024, 256>>>(p_ffn, w2, b2, p_res1, out, MTOK, DMODEL, FFN);

    (void)in_sizes; (void)n_in; (void)out_size;
}

// round 4
// speedup vs baseline: 1.6183x; 1.6183x over previous
#include <cuda_runtime.h>
#include <cuda_bf16.h>
#include <math.h>
#include <float.h>
#include <stdint.h>

// Problem dims (fixed)
#define BATCH 2
#define SEQ   2048
#define DMODEL 1024
#define NHEAD 16
#define HDIM  64
#define FFN   4096
#define MTOK  (BATCH*SEQ)          // 4096 token rows

typedef __nv_bfloat16 bf16;

// ---------------- scratch (allocation-free: __device__ globals) ----------------
__device__ float g_q   [MTOK*DMODEL];
__device__ float g_k   [MTOK*DMODEL];
__device__ float g_v   [MTOK*DMODEL];
__device__ float g_res1[MTOK*DMODEL];

__device__ bf16 g_ln1_hi[MTOK*DMODEL], g_ln1_lo[MTOK*DMODEL];
__device__ bf16 g_ctx_hi[MTOK*DMODEL], g_ctx_lo[MTOK*DMODEL];
__device__ bf16 g_ln2_hi[MTOK*DMODEL], g_ln2_lo[MTOK*DMODEL];
__device__ bf16 g_h1_hi [MTOK*FFN],    g_h1_lo [MTOK*FFN];

__device__ bf16 g_wqT_hi[DMODEL*DMODEL], g_wqT_lo[DMODEL*DMODEL];
__device__ bf16 g_wkT_hi[DMODEL*DMODEL], g_wkT_lo[DMODEL*DMODEL];
__device__ bf16 g_wvT_hi[DMODEL*DMODEL], g_wvT_lo[DMODEL*DMODEL];
__device__ bf16 g_woT_hi[DMODEL*DMODEL], g_woT_lo[DMODEL*DMODEL];
__device__ bf16 g_w1T_hi[DMODEL*FFN],    g_w1T_lo[DMODEL*FFN];
__device__ bf16 g_w2T_hi[FFN*DMODEL],    g_w2T_lo[FFN*DMODEL];

// ---------------- PTX helpers (baseline compute_103-safe: sm_80-era ops only) ----
__device__ __forceinline__ uint32_t smem_u32(const void* p) {
    uint32_t a;
    asm("{ .reg .u64 t; cvta.to.shared.u64 t, %1; cvt.u32.u64 %0, t; }" : "=r"(a) : "l"(p));
    return a;
}
__device__ __forceinline__ void cpa16(uint32_t dst, const void* src) {
    asm volatile("cp.async.cg.shared.global [%0], [%1], 16;" :: "r"(dst), "l"(src));
}
__device__ __forceinline__ void cpa_commit() { asm volatile("cp.async.commit_group;"); }
__device__ __forceinline__ void cpa_wait1()  { asm volatile("cp.async.wait_group 1;" ::: "memory"); }
__device__ __forceinline__ void cpa_wait0()  { asm volatile("cp.async.wait_group 0;" ::: "memory"); }

#define LDSM4(r, a) \
    asm volatile("ldmatrix.sync.aligned.m8n8.x4.shared.b16 {%0,%1,%2,%3}, [%4];" \
        : "=r"((r)[0]), "=r"((r)[1]), "=r"((r)[2]), "=r"((r)[3]) : "r"(a))

#define MMA_BF16(d, a, b0, b1) \
    asm volatile("mma.sync.aligned.m16n8k16.row.col.f32.bf16.bf16.f32 " \
        "{%0,%1,%2,%3}, {%4,%5,%6,%7}, {%8,%9}, {%0,%1,%2,%3};" \
        : "+f"((d)[0]), "+f"((d)[1]), "+f"((d)[2]), "+f"((d)[3]) \
        : "r"((a)[0]), "r"((a)[1]), "r"((a)[2]), "r"((a)[3]), "r"(b0), "r"(b1))

__device__ __forceinline__ float gelu_tanh(float x) {
    const float c = 0.7978845608028654f;
    float t = c * (x + 0.044715f * x * x * x);
    return 0.5f * x * (1.0f + tanhf(t));
}
__device__ __forceinline__ void split_hl(float v, bf16& h, bf16& l) {
    h = __float2bfloat16(v);
    l = __float2bfloat16(v - __bfloat162float(h));
}

// ---------------- LayerNorm -> hi/lo bf16 (torch var ddof=1) ----------------
__global__ __launch_bounds__(256)
void ln_hl_kernel(const float* __restrict__ x, const float* __restrict__ sc,
                  const float* __restrict__ sh, bf16* __restrict__ ohi, bf16* __restrict__ olo)
{
    int row = blockIdx.x;
    int tid = threadIdx.x;
    const float4 a = *(const float4*)&x[(size_t)row * DMODEL + tid * 4];

    float s = a.x + a.y + a.z + a.w;
    float q = a.x*a.x + a.y*a.y + a.z*a.z + a.w*a.w;
    #pragma unroll
    for (int off = 16; off > 0; off >>= 1) {
        s += __shfl_xor_sync(0xFFFFFFFFu, s, off);
        q += __shfl_xor_sync(0xFFFFFFFFu, q, off);
    }
    __shared__ float reds[8], redq[8], stats[2];
    int wid = tid >> 5, lane = tid & 31;
    if (lane == 0) { reds[wid] = s; redq[wid] = q; }
    __syncthreads();
    if (tid == 0) {
        float S = 0.f, Q = 0.f;
        #pragma unroll
        for (int i = 0; i < 8; i++) { S += reds[i]; Q += redq[i]; }
        float mean = S * (1.0f / DMODEL);
        float var  = (Q - S * mean) * (1.0f / (DMODEL - 1));
        stats[0] = mean;
        stats[1] = rsqrtf(var + 1e-5f);
    }
    __syncthreads();
    float mean = stats[0], rstd = stats[1];
    const float4 scv = *(const float4*)&sc[tid * 4];
    const float4 shv = *(const float4*)&sh[tid * 4];
    float o[4];
    o[0] = (a.x - mean) * rstd * scv.x + shv.x;
    o[1] = (a.y - mean) * rstd * scv.y + shv.y;
    o[2] = (a.z - mean) * rstd * scv.z + shv.z;
    o[3] = (a.w - mean) * rstd * scv.w + shv.w;

    union { bf16 b[4]; uint2 u; } uh, ul;
    #pragma unroll
    for (int i = 0; i < 4; i++) split_hl(o[i], uh.b[i], ul.b[i]);
    size_t idx = (size_t)row * DMODEL + tid * 4;
    *(uint2*)&ohi[idx] = uh.u;
    *(uint2*)&olo[idx] = ul.u;
}

// ---------------- weight transpose+convert: W[K,N] f32 -> WT hi/lo bf16 [N,K] ----------------
__global__ __launch_bounds__(256)
void wconvT(const float* __restrict__ W, bf16* __restrict__ ThT, bf16* __restrict__ TlT,
            int K, int N)
{
    __shared__ float t[32][33];
    int tx = threadIdx.x & 31, ty = threadIdx.x >> 5;   // 32 x 8
    int k0 = blockIdx.y * 32, n0 = blockIdx.x * 32;
    #pragma unroll
    for (int j = 0; j < 4; j++)
        t[ty + j * 8][tx] = W[(size_t)(k0 + ty + j * 8) * N + n0 + tx];
    __syncthreads();
    #pragma unroll
    for (int j = 0; j < 4; j++) {
        int n = n0 + ty + j * 8;
        float v = t[tx][ty + j * 8];
        bf16 h, l; split_hl(v, h, l);
        ThT[(size_t)n * K + k0 + tx] = h;
        TlT[(size_t)n * K + k0 + tx] = l;
    }
}

// ---------------- mma.sync bf16x3 GEMM: C[M,N] = A[M,K] @ B^T (B given as [N,K]) --
// CTA 128x128, BK=64, 256 threads, warp grid 2(M)x4(N), warp tile 64x32.
// D = Ahi*Bhi + Ahi*Blo + Alo*Bhi, fp32 accum.
// smem tile: 128 rows x 128B, swizzled off(row,c16) = row*128 + ((c16 ^ (row&7))<<4)
// EPI: 0 = fp32 out; 3 = +bias +res fp32 out; 2 = +bias, gelu -> hi/lo bf16 out
#define TILE_BYTES 16384
#define STAGE_BYTES (4*TILE_BYTES)        // Ahi, Alo, Bhi, Blo
#define GEMM_SMEM   (2*STAGE_BYTES)       // 131072

template<int EPI>
__global__ __launch_bounds__(256, 1)
void gemm_mma(const bf16* __restrict__ Ahi, const bf16* __restrict__ Alo,
              const bf16* __restrict__ Bhi, const bf16* __restrict__ Blo,
              const float* __restrict__ bias, const float* __restrict__ res,
              float* __restrict__ Cf, bf16* __restrict__ Chi, bf16* __restrict__ Clo,
              int M, int N, int K)
{
    extern __shared__ char smem[];
    const uint32_t sbase = smem_u32(smem);
    const int tid  = threadIdx.x;
    const int wid  = tid >> 5, lane = tid & 31;
    const int m0 = blockIdx.y * 128, n0 = blockIdx.x * 128;
    const int wm = (wid & 1) * 64, wn = (wid >> 1) * 32;

    const bf16* srcs[4];
    srcs[0] = Ahi + (size_t)m0 * K;
    srcs[1] = Alo + (size_t)m0 * K;
    srcs[2] = Bhi + (size_t)n0 * K;
    srcs[3] = Blo + (size_t)n0 * K;

    float acc[4][4][4];
    #pragma unroll
    for (int a = 0; a < 4; a++)
        #pragma unroll
        for (int b = 0; b < 4; b++)
            #pragma unroll
            for (int c = 0; c < 4; c++) acc[a][b][c] = 0.f;

    const int NC = K >> 6;

    auto load_stage = [&](int chunk, int stage) {
        const int k0 = chunk << 6;
        const uint32_t base = sbase + stage * STAGE_BYTES;
        #pragma unroll
        for (int j = 0; j < 16; j++) {
            const int tile = j >> 2;
            const int cid  = ((j & 3) << 8) + tid;   // 0..1023
            const int row  = cid >> 3;
            const int c    = cid & 7;
            uint32_t dst = base + tile * TILE_BYTES + row * 128 + ((c ^ (row & 7)) << 4);
            cpa16(dst, srcs[tile] + (size_t)row * K + k0 + c * 8);
        }
        cpa_commit();
    };

    load_stage(0, 0);
    load_stage(1, 1);

    for (int i = 0; i < NC; i++) {
        if (i < NC - 1) cpa_wait1(); else cpa_wait0();
        __syncthreads();
        const uint32_t tb = sbase + (i & 1) * STAGE_BYTES;

        #pragma unroll
        for (int ks = 0; ks < 4; ks++) {
            uint32_t ah[4][4], al[4][4], bh[2][4], bl[2][4];
            #pragma unroll
            for (int mt = 0; mt < 4; mt++) {
                int row = wm + mt * 16 + (lane & 15);
                int kg  = ks * 2 + (lane >> 4);
                uint32_t off = row * 128 + ((kg ^ (row & 7)) << 4);
                LDSM4(ah[mt], tb + off);
                LDSM4(al[mt], tb + TILE_BYTES + off);
            }
            #pragma unroll
            for (int bt = 0; bt < 2; bt++) {
                int row = wn + bt * 16 + ((lane >> 4) << 3) + (lane & 7);
                int kg  = ks * 2 + ((lane >> 3) & 1);
                uint32_t off = row * 128 + ((kg ^ (row & 7)) << 4);
                LDSM4(bh[bt], tb + 2 * TILE_BYTES + off);
                LDSM4(bl[bt], tb + 3 * TILE_BYTES + off);
            }
            #pragma unroll
            for (int mt = 0; mt < 4; mt++)
                #pragma unroll
                for (int nt = 0; nt < 4; nt++) {
                    uint32_t b0h = bh[nt >> 1][(nt & 1) * 2], b1h = bh[nt >> 1][(nt & 1) * 2 + 1];
                    uint32_t b0l = bl[nt >> 1][(nt & 1) * 2], b1l = bl[nt >> 1][(nt & 1) * 2 + 1];
                    MMA_BF16(acc[mt][nt], ah[mt], b0h, b1h);
                    MMA_BF16(acc[mt][nt], ah[mt], b0l, b1l);
                    MMA_BF16(acc[mt][nt], al[mt], b0h, b1h);
                }
        }
        __syncthreads();
        if (i + 2 < NC) load_stage(i + 2, i & 1);
    }

    // ---- epilogue (fragment layout: rows g, g+8; cols 2t, 2t+1) ----
    const int g = lane >> 2, t = lane & 3;
    #pragma unroll
    for (int mt = 0; mt < 4; mt++) {
        #pragma unroll
        for (int nt = 0; nt < 4; nt++) {
            const int gr0 = m0 + wm + mt * 16 + g;
            const int gr1 = gr0 + 8;
            const int gc  = n0 + wn + nt * 8 + 2 * t;
            float v00 = acc[mt][nt][0], v01 = acc[mt][nt][1];
            float v10 = acc[mt][nt][2], v11 = acc[mt][nt][3];
            if (EPI == 0) {
                *(float2*)&Cf[(size_t)gr0 * N + gc] = make_float2(v00, v01);
                *(float2*)&Cf[(size_t)gr1 * N + gc] = make_float2(v10, v11);
            } else if (EPI == 3) {
                const float2 bv  = *(const float2*)&bias[gc];
                const float2 r0v = *(const float2*)&res[(size_t)gr0 * N + gc];
                const float2 r1v = *(const float2*)&res[(size_t)gr1 * N + gc];
                *(float2*)&Cf[(size_t)gr0 * N + gc] =
                    make_float2(v00 + bv.x + r0v.x, v01 + bv.y + r0v.y);
                *(float2*)&Cf[(size_t)gr1 * N + gc] =
                    make_float2(v10 + bv.x + r1v.x, v11 + bv.y + r1v.y);
            } else { // EPI == 2: +bias, gelu -> hi/lo bf16
                const float2 bv = *(const float2*)&bias[gc];
                float x00 = gelu_tanh(v00 + bv.x), x01 = gelu_tanh(v01 + bv.y);
                float x10 = gelu_tanh(v10 + bv.x), x11 = gelu_tanh(v11 + bv.y);
                __nv_bfloat162 h0, l0, h1, l1;
                split_hl(x00, h0.x, l0.x); split_hl(x01, h0.y, l0.y);
                split_hl(x10, h1.x, l1.x); split_hl(x11, h1.y, l1.y);
                *(__nv_bfloat162*)&Chi[(size_t)gr0 * N + gc] = h0;
                *(__nv_bfloat162*)&Clo[(size_t)gr0 * N + gc] = l0;
                *(__nv_bfloat162*)&Chi[(size_t)gr1 * N + gc] = h1;
                *(__nv_bfloat162*)&Clo[(size_t)gr1 * N + gc] = l1;
            }
        }
    }
}

// ---------------- Flash attention (fp32, causal) -> ctx hi/lo bf16 ----------------
__global__ __launch_bounds__(128)
void attn_kernel(const float* __restrict__ q, const float* __restrict__ k,
                 const float* __restrict__ v, bf16* __restrict__ chi, bf16* __restrict__ clo)
{
    extern __shared__ float sm[];
    float* Qs = sm;
    float* Ks = sm + 4096;
    float* Vs = sm + 8192;
    float* Ss = sm + 12288;

    const int bh = blockIdx.y;
    const int b = bh >> 4;
    const int h = bh & 15;
    const int m0 = blockIdx.x * 64;
    const int tid = threadIdx.x;
    const int r = tid >> 1;
    const int half = tid & 1;
    const int dbase = half * 32;
    const float scale = 0.125f;
    const int gm = m0 + r;
    const size_t headoff = (size_t)h * HDIM;

    for (int i = tid; i < 1024; i += 128) {
        int rr = i >> 4, cc = (i & 15) * 4;
        *(float4*)&Qs[rr * 64 + cc] =
            *(const float4*)&q[((size_t)(b * SEQ + m0 + rr)) * DMODEL + headoff + cc];
    }
    __syncthreads();

    float4 qf[16];
    #pragma unroll
    for (int i = 0; i < 16; i++) qf[i] = *(const float4*)&Qs[r * 64 + i * 4];

    float acc[32];
    #pragma unroll
    for (int d = 0; d < 32; d++) acc[d] = 0.f;
    float mi = -INFINITY, li = 0.f;

    for (int n0 = 0; n0 <= m0; n0 += 64) {
        __syncthreads();
        for (int i = tid; i < 1024; i += 128) {
            int rr = i >> 4, cc = (i & 15) * 4;
            size_t gg = ((size_t)(b * SEQ + n0 + rr)) * DMODEL + headoff + cc;
            *(float4*)&Ks[rr * 64 + cc] = *(const float4*)&k[gg];
            *(float4*)&Vs[rr * 64 + cc] = *(const float4*)&v[gg];
        }
        __syncthreads();

        for (int n = dbase; n < dbase + 32; n++) {
            float s0 = 0.f, s1 = 0.f, s2 = 0.f, s3 = 0.f;
            #pragma unroll
            for (int i = 0; i < 16; i++) {
                float4 kf = *(const float4*)&Ks[n * 64 + i * 4];
                s0 += qf[i].x * kf.x; s1 += qf[i].y * kf.y;
                s2 += qf[i].z * kf.z; s3 += qf[i].w * kf.w;
            }
            float sv = (s0 + s1) + (s2 + s3);
            int gn = n0 + n;
            Ss[r * 64 + n] = (gn > gm) ? -INFINITY : sv * scale;
        }
        __syncthreads();

        float mt = -INFINITY;
        #pragma unroll
        for (int n = 0; n < 64; n++) mt = fmaxf(mt, Ss[r * 64 + n]);
        float mnew = fmaxf(mi, mt);
        float alpha = __expf(mi - mnew);
        li *= alpha;
        #pragma unroll
        for (int d = 0; d < 32; d++) acc[d] *= alpha;

        for (int n = 0; n < 64; n++) {
            float p = __expf(Ss[r * 64 + n] - mnew);
            li += p;
            #pragma unroll
            for (int i = 0; i < 8; i++) {
                float4 vf = *(const float4*)&Vs[n * 64 + dbase + i * 4];
                acc[i * 4 + 0] += p * vf.x;
                acc[i * 4 + 1] += p * vf.y;
                acc[i * 4 + 2] += p * vf.z;
                acc[i * 4 + 3] += p * vf.w;
            }
        }
        mi = mnew;
    }

    float inv = 1.0f / li;
    #pragma unroll
    for (int i = 0; i < 8; i++) {
        union { bf16 b[4]; uint2 u; } uh, ul;
        #pragma unroll
        for (int j = 0; j < 4; j++) split_hl(acc[i * 4 + j] * inv, uh.b[j], ul.b[j]);
        size_t oo = ((size_t)(b * SEQ + gm)) * DMODEL + headoff + dbase + i * 4;
        *(uint2*)&chi[oo] = uh.u;
        *(uint2*)&clo[oo] = ul.u;
    }
}

// ---------------- launch ----------------
extern "C" void kernel_launch(void* const* d_in, const int* in_sizes, int n_in,
                              void* d_out, int out_size)
{
    const float* x         = (const float*)d_in[0];
    const float* ln1_scale = (const float*)d_in[1];
    const float* ln1_shift = (const float*)d_in[2];
    const float* wq        = (const float*)d_in[3];
    const float* wk        = (const float*)d_in[4];
    const float* wv        = (const float*)d_in[5];
    const float* w_out     = (const float*)d_in[6];
    const float* b_out     = (const float*)d_in[7];
    const float* ln2_scale = (const float*)d_in[8];
    const float* ln2_shift = (const float*)d_in[9];
    const float* w1        = (const float*)d_in[10];
    const float* b1        = (const float*)d_in[11];
    const float* w2        = (const float*)d_in[12];
    const float* b2        = (const float*)d_in[13];
    float* out = (float*)d_out;

    float *p_q, *p_k, *p_v, *p_res1;
    bf16 *p_ln1h, *p_ln1l, *p_ctxh, *p_ctxl, *p_ln2h, *p_ln2l, *p_h1h, *p_h1l;
    bf16 *p_wqh, *p_wql, *p_wkh, *p_wkl, *p_wvh, *p_wvl, *p_woh, *p_wol;
    bf16 *p_w1h, *p_w1l, *p_w2h, *p_w2l;
    cudaGetSymbolAddress((void**)&p_q,    g_q);
    cudaGetSymbolAddress((void**)&p_k,    g_k);
    cudaGetSymbolAddress((void**)&p_v,    g_v);
    cudaGetSymbolAddress((void**)&p_res1, g_res1);
    cudaGetSymbolAddress((void**)&p_ln1h, g_ln1_hi);
    cudaGetSymbolAddress((void**)&p_ln1l, g_ln1_lo);
    cudaGetSymbolAddress((void**)&p_ctxh, g_ctx_hi);
    cudaGetSymbolAddress((void**)&p_ctxl, g_ctx_lo);
    cudaGetSymbolAddress((void**)&p_ln2h, g_ln2_hi);
    cudaGetSymbolAddress((void**)&p_ln2l, g_ln2_lo);
    cudaGetSymbolAddress((void**)&p_h1h,  g_h1_hi);
    cudaGetSymbolAddress((void**)&p_h1l,  g_h1_lo);
    cudaGetSymbolAddress((void**)&p_wqh,  g_wqT_hi);
    cudaGetSymbolAddress((void**)&p_wql,  g_wqT_lo);
    cudaGetSymbolAddress((void**)&p_wkh,  g_wkT_hi);
    cudaGetSymbolAddress((void**)&p_wkl,  g_wkT_lo);
    cudaGetSymbolAddress((void**)&p_wvh,  g_wvT_hi);
    cudaGetSymbolAddress((void**)&p_wvl,  g_wvT_lo);
    cudaGetSymbolAddress((void**)&p_woh,  g_woT_hi);
    cudaGetSymbolAddress((void**)&p_wol,  g_woT_lo);
    cudaGetSymbolAddress((void**)&p_w1h,  g_w1T_hi);
    cudaGetSymbolAddress((void**)&p_w1l,  g_w1T_lo);
    cudaGetSymbolAddress((void**)&p_w2h,  g_w2T_hi);
    cudaGetSymbolAddress((void**)&p_w2l,  g_w2T_lo);

    static bool attr_set = false;
    if (!attr_set) {
        cudaFuncSetAttribute(attn_kernel, cudaFuncAttributeMaxDynamicSharedMemorySize, 65536);
        cudaFuncSetAttribute(gemm_mma<0>, cudaFuncAttributeMaxDynamicSharedMemorySize, GEMM_SMEM);
        cudaFuncSetAttribute(gemm_mma<2>, cudaFuncAttributeMaxDynamicSharedMemorySize, GEMM_SMEM);
        cudaFuncSetAttribute(gemm_mma<3>, cudaFuncAttributeMaxDynamicSharedMemorySize, GEMM_SMEM);
        attr_set = true;
    }

    // 0) weight transpose + hi/lo convert
    wconvT<<<dim3(DMODEL/32, DMODEL/32), 256>>>(wq,    p_wqh, p_wql, DMODEL, DMODEL);
    wconvT<<<dim3(DMODEL/32, DMODEL/32), 256>>>(wk,    p_wkh, p_wkl, DMODEL, DMODEL);
    wconvT<<<dim3(DMODEL/32, DMODEL/32), 256>>>(wv,    p_wvh, p_wvl, DMODEL, DMODEL);
    wconvT<<<dim3(DMODEL/32, DMODEL/32), 256>>>(w_out, p_woh, p_wol, DMODEL, DMODEL);
    wconvT<<<dim3(FFN/32,    DMODEL/32), 256>>>(w1,    p_w1h, p_w1l, DMODEL, FFN);
    wconvT<<<dim3(DMODEL/32, FFN/32),    256>>>(w2,    p_w2h, p_w2l, FFN,    DMODEL);

    // 1) LN1 -> hi/lo
    ln_hl_kernel<<<MTOK, 256>>>(x, ln1_scale, ln1_shift, p_ln1h, p_ln1l);

    dim3 g1024(DMODEL/128, MTOK/128);   // (8, 32)
    dim3 g4096(FFN/128,    MTOK/128);   // (32, 32)

    // 2) Q/K/V projections (tensor core, bf16x3)
    gemm_mma<0><<<g1024, 256, GEMM_SMEM>>>(p_ln1h, p_ln1l, p_wqh, p_wql,
                                           nullptr, nullptr, p_q, nullptr, nullptr,
                                           MTOK, DMODEL, DMODEL);
    gemm_mma<0><<<g1024, 256, GEMM_SMEM>>>(p_ln1h, p_ln1l, p_wkh, p_wkl,
                                           nullptr, nullptr, p_k, nullptr, nullptr,
                                           MTOK, DMODEL, DMODEL);
    gemm_mma<0><<<g1024, 256, GEMM_SMEM>>>(p_ln1h, p_ln1l, p_wvh, p_wvl,
                                           nullptr, nullptr, p_v, nullptr, nullptr,
                                           MTOK, DMODEL, DMODEL);

    // 3) attention -> ctx hi/lo
    dim3 gAttn(SEQ/64, BATCH*NHEAD);
    attn_kernel<<<gAttn, 128, 65536>>>(p_q, p_k, p_v, p_ctxh, p_ctxl);

    // 4) out projection + bias + residual(x) -> res1 (fp32)
    gemm_mma<3><<<g1024, 256, GEMM_SMEM>>>(p_ctxh, p_ctxl, p_woh, p_wol,
                                           b_out, x, p_res1, nullptr, nullptr,
                                           MTOK, DMODEL, DMODEL);

    // 5) LN2 -> hi/lo
    ln_hl_kernel<<<MTOK, 256>>>(p_res1, ln2_scale, ln2_shift, p_ln2h, p_ln2l);

    // 6) FFN1 + bias + gelu -> h1 hi/lo
    gemm_mma<2><<<g4096, 256, GEMM_SMEM>>>(p_ln2h, p_ln2l, p_w1h, p_w1l,
                                           b1, nullptr, nullptr, p_h1h, p_h1l,
                                           MTOK, FFN, DMODEL);

    // 7) FFN2 + bias + residual(res1) -> out
    gemm_mma<3><<<g1024, 256, GEMM_SMEM>>>(p_h1h, p_h1l, p_w2h, p_w2l,
                                           b2, p_res1, out, nullptr, nullptr,
                                           MTOK, DMODEL, FFN);

    (void)in_sizes; (void)n_in; (void)out_size;
}

// round 6
// speedup vs baseline: 3.9971x; 2.4700x over previous
#include <cuda_runtime.h>
#include <cuda_bf16.h>
#include <math.h>
#include <float.h>
#include <stdint.h>

// Problem dims (fixed)
#define BATCH 2
#define SEQ   2048
#define DMODEL 1024
#define NHEAD 16
#define HDIM  64
#define FFN   4096
#define MTOK  (BATCH*SEQ)          // 4096 token rows

typedef __nv_bfloat16 bf16;

// ---------------- scratch (allocation-free: __device__ globals) ----------------
__device__ float g_res1[MTOK*DMODEL];

__device__ bf16 g_ln1_hi[MTOK*DMODEL], g_ln1_lo[MTOK*DMODEL];
__device__ bf16 g_q_hi  [MTOK*DMODEL], g_q_lo  [MTOK*DMODEL];
__device__ bf16 g_k_hi  [MTOK*DMODEL], g_k_lo  [MTOK*DMODEL];
__device__ bf16 g_vt_hi [MTOK*DMODEL], g_vt_lo [MTOK*DMODEL];   // [b*16+h][d][s]
__device__ bf16 g_ctx_hi[MTOK*DMODEL], g_ctx_lo[MTOK*DMODEL];
__device__ bf16 g_ln2_hi[MTOK*DMODEL], g_ln2_lo[MTOK*DMODEL];
__device__ bf16 g_h1_hi [MTOK*FFN],    g_h1_lo [MTOK*FFN];

__device__ bf16 g_wqT_hi[DMODEL*DMODEL], g_wqT_lo[DMODEL*DMODEL];
__device__ bf16 g_wkT_hi[DMODEL*DMODEL], g_wkT_lo[DMODEL*DMODEL];
__device__ bf16 g_wvT_hi[DMODEL*DMODEL], g_wvT_lo[DMODEL*DMODEL];
__device__ bf16 g_woT_hi[DMODEL*DMODEL], g_woT_lo[DMODEL*DMODEL];
__device__ bf16 g_w1T_hi[DMODEL*FFN],    g_w1T_lo[DMODEL*FFN];
__device__ bf16 g_w2T_hi[FFN*DMODEL],    g_w2T_lo[FFN*DMODEL];

// ---------------- PTX helpers (baseline compute_103-safe: sm_80-era ops only) ----
__device__ __forceinline__ uint32_t smem_u32(const void* p) {
    uint32_t a;
    asm("{ .reg .u64 t; cvta.to.shared.u64 t, %1; cvt.u32.u64 %0, t; }" : "=r"(a) : "l"(p));
    return a;
}
__device__ __forceinline__ void cpa16(uint32_t dst, const void* src) {
    asm volatile("cp.async.cg.shared.global [%0], [%1], 16;" :: "r"(dst), "l"(src));
}
__device__ __forceinline__ void cpa_commit() { asm volatile("cp.async.commit_group;"); }
__device__ __forceinline__ void cpa_wait2()  { asm volatile("cp.async.wait_group 2;" ::: "memory"); }
__device__ __forceinline__ void cpa_wait1()  { asm volatile("cp.async.wait_group 1;" ::: "memory"); }
__device__ __forceinline__ void cpa_wait0()  { asm volatile("cp.async.wait_group 0;" ::: "memory"); }

#define LDSM4(r, a) \
    asm volatile("ldmatrix.sync.aligned.m8n8.x4.shared.b16 {%0,%1,%2,%3}, [%4];" \
        : "=r"((r)[0]), "=r"((r)[1]), "=r"((r)[2]), "=r"((r)[3]) : "r"(a))

#define MMA_BF16(d, a, b0, b1) \
    asm volatile("mma.sync.aligned.m16n8k16.row.col.f32.bf16.bf16.f32 " \
        "{%0,%1,%2,%3}, {%4,%5,%6,%7}, {%8,%9}, {%0,%1,%2,%3};" \
        : "+f"((d)[0]), "+f"((d)[1]), "+f"((d)[2]), "+f"((d)[3]) \
        : "r"((a)[0]), "r"((a)[1]), "r"((a)[2]), "r"((a)[3]), "r"(b0), "r"(b1))

__device__ __forceinline__ float gelu_tanh(float x) {
    const float c = 0.7978845608028654f;
    float t = c * (x + 0.044715f * x * x * x);
    return 0.5f * x * (1.0f + tanhf(t));
}
__device__ __forceinline__ void split_hl(float v, bf16& h, bf16& l) {
    h = __float2bfloat16(v);
    l = __float2bfloat16(v - __bfloat162float(h));
}
__device__ __forceinline__ uint32_t pk2(float x, float y) {
    __nv_bfloat162 t;
    t.x = __float2bfloat16(x);
    t.y = __float2bfloat16(y);
    return *(uint32_t*)&t;
}

// ---------------- LayerNorm -> hi/lo bf16 (torch var ddof=1) ----------------
__global__ __launch_bounds__(256)
void ln_hl_kernel(const float* __restrict__ x, const float* __restrict__ sc,
                  const float* __restrict__ sh, bf16* __restrict__ ohi, bf16* __restrict__ olo)
{
    int row = blockIdx.x;
    int tid = threadIdx.x;
    const float4 a = *(const float4*)&x[(size_t)row * DMODEL + tid * 4];

    float s = a.x + a.y + a.z + a.w;
    float q = a.x*a.x + a.y*a.y + a.z*a.z + a.w*a.w;
    #pragma unroll
    for (int off = 16; off > 0; off >>= 1) {
        s += __shfl_xor_sync(0xFFFFFFFFu, s, off);
        q += __shfl_xor_sync(0xFFFFFFFFu, q, off);
    }
    __shared__ float reds[8], redq[8], stats[2];
    int wid = tid >> 5, lane = tid & 31;
    if (lane == 0) { reds[wid] = s; redq[wid] = q; }
    __syncthreads();
    if (tid == 0) {
        float S = 0.f, Q = 0.f;
        #pragma unroll
        for (int i = 0; i < 8; i++) { S += reds[i]; Q += redq[i]; }
        float mean = S * (1.0f / DMODEL);
        float var  = (Q - S * mean) * (1.0f / (DMODEL - 1));
        stats[0] = mean;
        stats[1] = rsqrtf(var + 1e-5f);
    }
    __syncthreads();
    float mean = stats[0], rstd = stats[1];
    const float4 scv = *(const float4*)&sc[tid * 4];
    const float4 shv = *(const float4*)&sh[tid * 4];
    float o[4];
    o[0] = (a.x - mean) * rstd * scv.x + shv.x;
    o[1] = (a.y - mean) * rstd * scv.y + shv.y;
    o[2] = (a.z - mean) * rstd * scv.z + shv.z;
    o[3] = (a.w - mean) * rstd * scv.w + shv.w;

    union { bf16 b[4]; uint2 u; } uh, ul;
    #pragma unroll
    for (int i = 0; i < 4; i++) split_hl(o[i], uh.b[i], ul.b[i]);
    size_t idx = (size_t)row * DMODEL + tid * 4;
    *(uint2*)&ohi[idx] = uh.u;
    *(uint2*)&olo[idx] = ul.u;
}

// ---------------- weight transpose+convert: W[K,N] f32 -> WT hi/lo bf16 [N,K] ----------------
__global__ __launch_bounds__(256)
void wconvT(const float* __restrict__ W, bf16* __restrict__ ThT, bf16* __restrict__ TlT,
            int K, int N)
{
    __shared__ float t[32][33];
    int tx = threadIdx.x & 31, ty = threadIdx.x >> 5;   // 32 x 8
    int k0 = blockIdx.y * 32, n0 = blockIdx.x * 32;
    #pragma unroll
    for (int j = 0; j < 4; j++)
        t[ty + j * 8][tx] = W[(size_t)(k0 + ty + j * 8) * N + n0 + tx];
    __syncthreads();
    #pragma unroll
    for (int j = 0; j < 4; j++) {
        int n = n0 + ty + j * 8;
        float v = t[tx][ty + j * 8];
        bf16 h, l; split_hl(v, h, l);
        ThT[(size_t)n * K + k0 + tx] = h;
        TlT[(size_t)n * K + k0 + tx] = l;
    }
}

// ---------------- mma.sync bf16x3 GEMM: C[M,N] = A[M,K] @ B^T (B given as [N,K]) --
// CTA 128x128, BK=64, 256 threads, warp grid 2(M)x4(N), warp tile 64x32.
// EPI: 1 = hi/lo bf16 out (no bias); 2 = +bias,gelu -> hi/lo bf16;
//      3 = +bias +res -> fp32; 4 = hi/lo bf16 out, V-transposed per-head
#define TILE_BYTES 16384
#define STAGE_BYTES (4*TILE_BYTES)
#define GEMM_SMEM   (2*STAGE_BYTES)

template<int EPI>
__global__ __launch_bounds__(256, 1)
void gemm_mma(const bf16* __restrict__ Ahi, const bf16* __restrict__ Alo,
              const bf16* __restrict__ Bhi, const bf16* __restrict__ Blo,
              const float* __restrict__ bias, const float* __restrict__ res,
              float* __restrict__ Cf, bf16* __restrict__ Chi, bf16* __restrict__ Clo,
              int M, int N, int K)
{
    extern __shared__ char smem[];
    const uint32_t sbase = smem_u32(smem);
    const int tid  = threadIdx.x;
    const int wid  = tid >> 5, lane = tid & 31;
    const int m0 = blockIdx.y * 128, n0 = blockIdx.x * 128;
    const int wm = (wid & 1) * 64, wn = (wid >> 1) * 32;

    const bf16* srcs[4];
    srcs[0] = Ahi + (size_t)m0 * K;
    srcs[1] = Alo + (size_t)m0 * K;
    srcs[2] = Bhi + (size_t)n0 * K;
    srcs[3] = Blo + (size_t)n0 * K;

    float acc[4][4][4];
    #pragma unroll
    for (int a = 0; a < 4; a++)
        #pragma unroll
        for (int b = 0; b < 4; b++)
            #pragma unroll
            for (int c = 0; c < 4; c++) acc[a][b][c] = 0.f;

    const int NC = K >> 6;

    auto load_stage = [&](int chunk, int stage) {
        const int k0 = chunk << 6;
        const uint32_t base = sbase + stage * STAGE_BYTES;
        #pragma unroll
        for (int j = 0; j < 16; j++) {
            const int tile = j >> 2;
            const int cid  = ((j & 3) << 8) + tid;
            const int row  = cid >> 3;
            const int c    = cid & 7;
            uint32_t dst = base + tile * TILE_BYTES + row * 128 + ((c ^ (row & 7)) << 4);
            cpa16(dst, srcs[tile] + (size_t)row * K + k0 + c * 8);
        }
        cpa_commit();
    };

    load_stage(0, 0);
    load_stage(1, 1);

    for (int i = 0; i < NC; i++) {
        if (i < NC - 1) cpa_wait1(); else cpa_wait0();
        __syncthreads();
        const uint32_t tb = sbase + (i & 1) * STAGE_BYTES;

        #pragma unroll
        for (int ks = 0; ks < 4; ks++) {
            uint32_t ah[4][4], al[4][4], bh[2][4], bl[2][4];
            #pragma unroll
            for (int mt = 0; mt < 4; mt++) {
                int row = wm + mt * 16 + (lane & 15);
                int kg  = ks * 2 + (lane >> 4);
                uint32_t off = row * 128 + ((kg ^ (row & 7)) << 4);
                LDSM4(ah[mt], tb + off);
                LDSM4(al[mt], tb + TILE_BYTES + off);
            }
            #pragma unroll
            for (int bt = 0; bt < 2; bt++) {
                int row = wn + bt * 16 + ((lane >> 4) << 3) + (lane & 7);
                int kg  = ks * 2 + ((lane >> 3) & 1);
                uint32_t off = row * 128 + ((kg ^ (row & 7)) << 4);
                LDSM4(bh[bt], tb + 2 * TILE_BYTES + off);
                LDSM4(bl[bt], tb + 3 * TILE_BYTES + off);
            }
            #pragma unroll
            for (int mt = 0; mt < 4; mt++)
                #pragma unroll
                for (int nt = 0; nt < 4; nt++) {
                    uint32_t b0h = bh[nt >> 1][(nt & 1) * 2], b1h = bh[nt >> 1][(nt & 1) * 2 + 1];
                    uint32_t b0l = bl[nt >> 1][(nt & 1) * 2], b1l = bl[nt >> 1][(nt & 1) * 2 + 1];
                    MMA_BF16(acc[mt][nt], ah[mt], b0h, b1h);
                    MMA_BF16(acc[mt][nt], ah[mt], b0l, b1l);
                    MMA_BF16(acc[mt][nt], al[mt], b0h, b1h);
                }
        }
        __syncthreads();
        if (i + 2 < NC) load_stage(i + 2, i & 1);
    }

    // ---- epilogue (fragment: rows g, g+8; cols 2t, 2t+1) ----
    const int g = lane >> 2, t = lane & 3;
    #pragma unroll
    for (int mt = 0; mt < 4; mt++) {
        #pragma unroll
        for (int nt = 0; nt < 4; nt++) {
            const int gr0 = m0 + wm + mt * 16 + g;
            const int gr1 = gr0 + 8;
            const int gc  = n0 + wn + nt * 8 + 2 * t;
            float v00 = acc[mt][nt][0], v01 = acc[mt][nt][1];
            float v10 = acc[mt][nt][2], v11 = acc[mt][nt][3];
            if (EPI == 1) {
                __nv_bfloat162 h0, l0, h1, l1;
                split_hl(v00, h0.x, l0.x); split_hl(v01, h0.y, l0.y);
                split_hl(v10, h1.x, l1.x); split_hl(v11, h1.y, l1.y);
                *(__nv_bfloat162*)&Chi[(size_t)gr0 * N + gc] = h0;
                *(__nv_bfloat162*)&Clo[(size_t)gr0 * N + gc] = l0;
                *(__nv_bfloat162*)&Chi[(size_t)gr1 * N + gc] = h1;
                *(__nv_bfloat162*)&Clo[(size_t)gr1 * N + gc] = l1;
            } else if (EPI == 3) {
                const float2 bv  = *(const float2*)&bias[gc];
                const float2 r0v = *(const float2*)&res[(size_t)gr0 * N + gc];
                const float2 r1v = *(const float2*)&res[(size_t)gr1 * N + gc];
                *(float2*)&Cf[(size_t)gr0 * N + gc] =
                    make_float2(v00 + bv.x + r0v.x, v01 + bv.y + r0v.y);
                *(float2*)&Cf[(size_t)gr1 * N + gc] =
                    make_float2(v10 + bv.x + r1v.x, v11 + bv.y + r1v.y);
            } else if (EPI == 2) {
                const float2 bv = *(const float2*)&bias[gc];
                float x00 = gelu_tanh(v00 + bv.x), x01 = gelu_tanh(v01 + bv.y);
                float x10 = gelu_tanh(v10 + bv.x), x11 = gelu_tanh(v11 + bv.y);
                __nv_bfloat162 h0, l0, h1, l1;
                split_hl(x00, h0.x, l0.x); split_hl(x01, h0.y, l0.y);
                split_hl(x10, h1.x, l1.x); split_hl(x11, h1.y, l1.y);
                *(__nv_bfloat162*)&Chi[(size_t)gr0 * N + gc] = h0;
                *(__nv_bfloat162*)&Clo[(size_t)gr0 * N + gc] = l0;
                *(__nv_bfloat162*)&Chi[(size_t)gr1 * N + gc] = h1;
                *(__nv_bfloat162*)&Clo[(size_t)gr1 * N + gc] = l1;
            } else { // EPI == 4: V transposed per-head: [b*16+h][d][s]
                #pragma unroll
                for (int e = 0; e < 4; e++) {
                    int gr = (e < 2) ? gr0 : gr1;
                    int gcc = gc + (e & 1);
                    float v = (e == 0) ? v00 : (e == 1) ? v01 : (e == 2) ? v10 : v11;
                    int b  = gr >> 11, s = gr & 2047;
                    int h  = gcc >> 6, d = gcc & 63;
                    size_t o = ((size_t)((b * 16 + h) * 64 + d)) * 2048 + s;
                    bf16 hh, ll; split_hl(v, hh, ll);
                    Chi[o] = hh;
                    Clo[o] = ll;
                }
            }
        }
    }
}

// ---------------- mma.sync flash attention (bf16x3, causal) -> ctx hi/lo ----------
// CTA: 64 q-rows x one (b,h). 128 threads = 4 warps x 16 rows.
// smem: Qhi,Qlo @0,8192; stages @16384 + s*32768: Khi,Klo,Vthi,Vtlo (8KB each)
#define ATT_SMEM (16384 + 2*32768)

__global__ __launch_bounds__(128, 1)
void attn_mma(const bf16* __restrict__ qhi, const bf16* __restrict__ qlo,
              const bf16* __restrict__ khi, const bf16* __restrict__ klo,
              const bf16* __restrict__ vthi, const bf16* __restrict__ vtlo,
              bf16* __restrict__ chi, bf16* __restrict__ clo)
{
    extern __shared__ char smem[];
    const uint32_t sbase = smem_u32(smem);
    const int tid  = threadIdx.x;
    const int wid  = tid >> 5, lane = tid & 31;
    const int g = lane >> 2, t = lane & 3;
    const int bh = blockIdx.y;
    const int b = bh >> 4, h = bh & 15;
    const int m0 = blockIdx.x * 64;
    const int nit = m0 / 64 + 1;

    // ---- load Q tile (hi/lo) ----
    {
        const bf16* qs[2] = { qhi + ((size_t)(b * SEQ + m0)) * DMODEL + h * 64,
                              qlo + ((size_t)(b * SEQ + m0)) * DMODEL + h * 64 };
        #pragma unroll
        for (int tl = 0; tl < 2; tl++)
            #pragma unroll
            for (int j = 0; j < 4; j++) {
                int cid = j * 128 + tid;
                int row = cid >> 3, c = cid & 7;
                cpa16(sbase + tl * 8192 + row * 128 + ((c ^ (row & 7)) << 4),
                      qs[tl] + (size_t)row * DMODEL + c * 8);
            }
        cpa_commit();
    }

    auto load_kv = [&](int it, int stage) {
        int n0 = it * 64; if (n0 > m0) n0 = m0;
        const uint32_t base = sbase + 16384 + stage * 32768;
        const bf16* ks_[2] = { khi + ((size_t)(b * SEQ + n0)) * DMODEL + h * 64,
                               klo + ((size_t)(b * SEQ + n0)) * DMODEL + h * 64 };
        const bf16* vs_[2] = { vthi + ((size_t)(bh * 64)) * 2048 + n0,
                               vtlo + ((size_t)(bh * 64)) * 2048 + n0 };
        #pragma unroll
        for (int tl = 0; tl < 2; tl++)
            #pragma unroll
            for (int j = 0; j < 4; j++) {
                int cid = j * 128 + tid;
                int row = cid >> 3, c = cid & 7;
                uint32_t sw = row * 128 + ((c ^ (row & 7)) << 4);
                cpa16(base + tl * 8192 + sw,         ks_[tl] + (size_t)row * DMODEL + c * 8);
                cpa16(base + 16384 + tl * 8192 + sw, vs_[tl] + (size_t)row * 2048 + c * 8);
            }
        cpa_commit();
    };

    load_kv(0, 0);
    load_kv(1, 1);

    // Q fragments (constant across iters)
    cpa_wait2();
    __syncthreads();
    uint32_t qh[4][4], ql[4][4];
    #pragma unroll
    for (int ks = 0; ks < 4; ks++) {
        int row = wid * 16 + (lane & 15);
        int kg  = ks * 2 + (lane >> 4);
        uint32_t off = row * 128 + ((kg ^ (row & 7)) << 4);
        LDSM4(qh[ks], sbase + off);
        LDSM4(ql[ks], sbase + 8192 + off);
    }

    float m[2] = { -INFINITY, -INFINITY };
    float l[2] = { 0.f, 0.f };
    float acc_o[8][4];
    #pragma unroll
    for (int i = 0; i < 8; i++)
        #pragma unroll
        for (int c = 0; c < 4; c++) acc_o[i][c] = 0.f;

    const int row0 = wid * 16 + g;     // local q row (thread's first row)

    for (int it = 0; it < nit; it++) {
        if (it < nit - 1) cpa_wait1(); else cpa_wait0();
        __syncthreads();
        const uint32_t kb = sbase + 16384 + (it & 1) * 32768;
        const uint32_t vb = kb + 16384;
        const bool diag = (it == nit - 1);   // n0 == m0 block

        // ---- S = Q K^T (bf16x3) ----
        float s[8][4];
        #pragma unroll
        for (int i = 0; i < 8; i++)
            #pragma unroll
            for (int c = 0; c < 4; c++) s[i][c] = 0.f;

        #pragma unroll
        for (int ks = 0; ks < 4; ks++) {
            uint32_t kh[4][4], kl[4][4];
            #pragma unroll
            for (int bt = 0; bt < 4; bt++) {
                int row = bt * 16 + ((lane >> 4) << 3) + (lane & 7);
                int kg  = ks * 2 + ((lane >> 3) & 1);
                uint32_t off = row * 128 + ((kg ^ (row & 7)) << 4);
                LDSM4(kh[bt], kb + off);
                LDSM4(kl[bt], kb + 8192 + off);
            }
            #pragma unroll
            for (int nt = 0; nt < 8; nt++) {
                uint32_t b0h = kh[nt >> 1][(nt & 1) * 2], b1h = kh[nt >> 1][(nt & 1) * 2 + 1];
                uint32_t b0l = kl[nt >> 1][(nt & 1) * 2], b1l = kl[nt >> 1][(nt & 1) * 2 + 1];
                MMA_BF16(s[nt], qh[ks], b0h, b1h);
                MMA_BF16(s[nt], qh[ks], b0l, b1l);
                MMA_BF16(s[nt], ql[ks], b0h, b1h);
            }
        }

        // ---- scale + causal mask + online softmax ----
        #pragma unroll
        for (int nt = 0; nt < 8; nt++) {
            #pragma unroll
            for (int c = 0; c < 4; c++) {
                int colL = nt * 8 + 2 * t + (c & 1);
                int rowL = row0 + ((c >> 1) << 3);
                float v = s[nt][c] * 0.125f;
                if (diag && colL > rowL) v = -INFINITY;
                s[nt][c] = v;
            }
        }
        float mx0 = -INFINITY, mx1 = -INFINITY;
        #pragma unroll
        for (int nt = 0; nt < 8; nt++) {
            mx0 = fmaxf(mx0, fmaxf(s[nt][0], s[nt][1]));
            mx1 = fmaxf(mx1, fmaxf(s[nt][2], s[nt][3]));
        }
        mx0 = fmaxf(mx0, __shfl_xor_sync(0xFFFFFFFFu, mx0, 1));
        mx0 = fmaxf(mx0, __shfl_xor_sync(0xFFFFFFFFu, mx0, 2));
        mx1 = fmaxf(mx1, __shfl_xor_sync(0xFFFFFFFFu, mx1, 1));
        mx1 = fmaxf(mx1, __shfl_xor_sync(0xFFFFFFFFu, mx1, 2));
        float mn0 = fmaxf(m[0], mx0), mn1 = fmaxf(m[1], mx1);
        float a0 = __expf(m[0] - mn0), a1 = __expf(m[1] - mn1);
        m[0] = mn0; m[1] = mn1;
        #pragma unroll
        for (int i = 0; i < 8; i++) {
            acc_o[i][0] *= a0; acc_o[i][1] *= a0;
            acc_o[i][2] *= a1; acc_o[i][3] *= a1;
        }
        float sum0 = 0.f, sum1 = 0.f;
        float p[8][4];
        #pragma unroll
        for (int nt = 0; nt < 8; nt++) {
            p[nt][0] = __expf(s[nt][0] - mn0); p[nt][1] = __expf(s[nt][1] - mn0);
            p[nt][2] = __expf(s[nt][2] - mn1); p[nt][3] = __expf(s[nt][3] - mn1);
            sum0 += p[nt][0] + p[nt][1];
            sum1 += p[nt][2] + p[nt][3];
        }
        sum0 += __shfl_xor_sync(0xFFFFFFFFu, sum0, 1);
        sum0 += __shfl_xor_sync(0xFFFFFFFFu, sum0, 2);
        sum1 += __shfl_xor_sync(0xFFFFFFFFu, sum1, 1);
        sum1 += __shfl_xor_sync(0xFFFFFFFFu, sum1, 2);
        l[0] = l[0] * a0 + sum0;
        l[1] = l[1] * a1 + sum1;

        // ---- O += P V (bf16x3); P split hi/lo in-register ----
        #pragma unroll
        for (int ks2 = 0; ks2 < 4; ks2++) {
            // A-frags of P for key chunk ks2*16 (= S n-tiles 2ks2, 2ks2+1)
            float ph[8], pl[8];
            #pragma unroll
            for (int e = 0; e < 2; e++) {
                int nt = 2 * ks2 + e;
                #pragma unroll
                for (int c = 0; c < 4; c++) {
                    bf16 hh, ll; split_hl(p[nt][c], hh, ll);
                    ph[e * 4 + c] = __bfloat162float(hh);
                    pl[e * 4 + c] = p[nt][c] - ph[e * 4 + c];
                }
            }
            uint32_t pah[4], pal[4];
            pah[0] = pk2(ph[0], ph[1]); pah[1] = pk2(ph[2], ph[3]);
            pah[2] = pk2(ph[4], ph[5]); pah[3] = pk2(ph[6], ph[7]);
            pal[0] = pk2(pl[0], pl[1]); pal[1] = pk2(pl[2], pl[3]);
            pal[2] = pk2(pl[4], pl[5]); pal[3] = pk2(pl[6], pl[7]);

            uint32_t vh[4][4], vl[4][4];
            #pragma unroll
            for (int dt = 0; dt < 4; dt++) {
                int row = dt * 16 + ((lane >> 4) << 3) + (lane & 7);
                int kg  = ks2 * 2 + ((lane >> 3) & 1);
                uint32_t off = row * 128 + ((kg ^ (row & 7)) << 4);
                LDSM4(vh[dt], vb + off);
                LDSM4(vl[dt], vb + 8192 + off);
            }
            #pragma unroll
            for (int nt = 0; nt < 8; nt++) {
                uint32_t b0h = vh[nt >> 1][(nt & 1) * 2], b1h = vh[nt >> 1][(nt & 1) * 2 + 1];
                uint32_t b0l = vl[nt >> 1][(nt & 1) * 2], b1l = vl[nt >> 1][(nt & 1) * 2 + 1];
                MMA_BF16(acc_o[nt], pah, b0h, b1h);
                MMA_BF16(acc_o[nt], pah, b0l, b1l);
                MMA_BF16(acc_o[nt], pal, b0h, b1h);
            }
        }

        __syncthreads();
        if (it + 2 < nit) load_kv(it + 2, it & 1);
    }

    // ---- epilogue ----
    float inv0 = 1.0f / l[0], inv1 = 1.0f / l[1];
    const size_t gr0 = (size_t)(b * SEQ + m0 + wid * 16 + g) * DMODEL + h * 64;
    const size_t gr1 = gr0 + 8 * DMODEL;
    #pragma unroll
    for (int nt = 0; nt < 8; nt++) {
        int gc = nt * 8 + 2 * t;
        __nv_bfloat162 h0, l0h, h1, l1h;
        split_hl(acc_o[nt][0] * inv0, h0.x, l0h.x);
        split_hl(acc_o[nt][1] * inv0, h0.y, l0h.y);
        split_hl(acc_o[nt][2] * inv1, h1.x, l1h.x);
        split_hl(acc_o[nt][3] * inv1, h1.y, l1h.y);
        *(__nv_bfloat162*)&chi[gr0 + gc] = h0;
        *(__nv_bfloat162*)&clo[gr0 + gc] = l0h;
        *(__nv_bfloat162*)&chi[gr1 + gc] = h1;
        *(__nv_bfloat162*)&clo[gr1 + gc] = l1h;
    }
}

// ---------------- launch ----------------
extern "C" void kernel_launch(void* const* d_in, const int* in_sizes, int n_in,
                              void* d_out, int out_size)
{
    const float* x         = (const float*)d_in[0];
    const float* ln1_scale = (const float*)d_in[1];
    const float* ln1_shift = (const float*)d_in[2];
    const float* wq        = (const float*)d_in[3];
    const float* wk        = (const float*)d_in[4];
    const float* wv        = (const float*)d_in[5];
    const float* w_out     = (const float*)d_in[6];
    const float* b_out     = (const float*)d_in[7];
    const float* ln2_scale = (const float*)d_in[8];
    const float* ln2_shift = (const float*)d_in[9];
    const float* w1        = (const float*)d_in[10];
    const float* b1        = (const float*)d_in[11];
    const float* w2        = (const float*)d_in[12];
    const float* b2        = (const float*)d_in[13];
    float* out = (float*)d_out;

    float *p_res1;
    bf16 *p_ln1h, *p_ln1l, *p_qh, *p_ql, *p_kh, *p_kl, *p_vth, *p_vtl;
    bf16 *p_ctxh, *p_ctxl, *p_ln2h, *p_ln2l, *p_h1h, *p_h1l;
    bf16 *p_wqh, *p_wql, *p_wkh, *p_wkl, *p_wvh, *p_wvl, *p_woh, *p_wol;
    bf16 *p_w1h, *p_w1l, *p_w2h, *p_w2l;
    cudaGetSymbolAddress((void**)&p_res1, g_res1);
    cudaGetSymbolAddress((void**)&p_ln1h, g_ln1_hi);
    cudaGetSymbolAddress((void**)&p_ln1l, g_ln1_lo);
    cudaGetSymbolAddress((void**)&p_qh,   g_q_hi);
    cudaGetSymbolAddress((void**)&p_ql,   g_q_lo);
    cudaGetSymbolAddress((void**)&p_kh,   g_k_hi);
    cudaGetSymbolAddress((void**)&p_kl,   g_k_lo);
    cudaGetSymbolAddress((void**)&p_vth,  g_vt_hi);
    cudaGetSymbolAddress((void**)&p_vtl,  g_vt_lo);
    cudaGetSymbolAddress((void**)&p_ctxh, g_ctx_hi);
    cudaGetSymbolAddress((void**)&p_ctxl, g_ctx_lo);
    cudaGetSymbolAddress((void**)&p_ln2h, g_ln2_hi);
    cudaGetSymbolAddress((void**)&p_ln2l, g_ln2_lo);
    cudaGetSymbolAddress((void**)&p_h1h,  g_h1_hi);
    cudaGetSymbolAddress((void**)&p_h1l,  g_h1_lo);
    cudaGetSymbolAddress((void**)&p_wqh,  g_wqT_hi);
    cudaGetSymbolAddress((void**)&p_wql,  g_wqT_lo);
    cudaGetSymbolAddress((void**)&p_wkh,  g_wkT_hi);
    cudaGetSymbolAddress((void**)&p_wkl,  g_wkT_lo);
    cudaGetSymbolAddress((void**)&p_wvh,  g_wvT_hi);
    cudaGetSymbolAddress((void**)&p_wvl,  g_wvT_lo);
    cudaGetSymbolAddress((void**)&p_woh,  g_woT_hi);
    cudaGetSymbolAddress((void**)&p_wol,  g_woT_lo);
    cudaGetSymbolAddress((void**)&p_w1h,  g_w1T_hi);
    cudaGetSymbolAddress((void**)&p_w1l,  g_w1T_lo);
    cudaGetSymbolAddress((void**)&p_w2h,  g_w2T_hi);
    cudaGetSymbolAddress((void**)&p_w2l,  g_w2T_lo);

    static bool attr_set = false;
    if (!attr_set) {
        cudaFuncSetAttribute(attn_mma,    cudaFuncAttributeMaxDynamicSharedMemorySize, ATT_SMEM);
        cudaFuncSetAttribute(gemm_mma<1>, cudaFuncAttributeMaxDynamicSharedMemorySize, GEMM_SMEM);
        cudaFuncSetAttribute(gemm_mma<2>, cudaFuncAttributeMaxDynamicSharedMemorySize, GEMM_SMEM);
        cudaFuncSetAttribute(gemm_mma<3>, cudaFuncAttributeMaxDynamicSharedMemorySize, GEMM_SMEM);
        cudaFuncSetAttribute(gemm_mma<4>, cudaFuncAttributeMaxDynamicSharedMemorySize, GEMM_SMEM);
        attr_set = true;
    }

    // 0) weight transpose + hi/lo convert
    wconvT<<<dim3(DMODEL/32, DMODEL/32), 256>>>(wq,    p_wqh, p_wql, DMODEL, DMODEL);
    wconvT<<<dim3(DMODEL/32, DMODEL/32), 256>>>(wk,    p_wkh, p_wkl, DMODEL, DMODEL);
    wconvT<<<dim3(DMODEL/32, DMODEL/32), 256>>>(wv,    p_wvh, p_wvl, DMODEL, DMODEL);
    wconvT<<<dim3(DMODEL/32, DMODEL/32), 256>>>(w_out, p_woh, p_wol, DMODEL, DMODEL);
    wconvT<<<dim3(FFN/32,    DMODEL/32), 256>>>(w1,    p_w1h, p_w1l, DMODEL, FFN);
    wconvT<<<dim3(DMODEL/32, FFN/32),    256>>>(w2,    p_w2h, p_w2l, FFN,    DMODEL);

    // 1) LN1 -> hi/lo
    ln_hl_kernel<<<MTOK, 256>>>(x, ln1_scale, ln1_shift, p_ln1h, p_ln1l);

    dim3 g1024(DMODEL/128, MTOK/128);
    dim3 g4096(FFN/128,    MTOK/128);

    // 2) Q/K/V projections -> hi/lo bf16 (V transposed per-head)
    gemm_mma<1><<<g1024, 256, GEMM_SMEM>>>(p_ln1h, p_ln1l, p_wqh, p_wql,
                                           nullptr, nullptr, nullptr, p_qh, p_ql,
                                           MTOK, DMODEL, DMODEL);
    gemm_mma<1><<<g1024, 256, GEMM_SMEM>>>(p_ln1h, p_ln1l, p_wkh, p_wkl,
                                           nullptr, nullptr, nullptr, p_kh, p_kl,
                                           MTOK, DMODEL, DMODEL);
    gemm_mma<4><<<g1024, 256, GEMM_SMEM>>>(p_ln1h, p_ln1l, p_wvh, p_wvl,
                                           nullptr, nullptr, nullptr, p_vth, p_vtl,
                                           MTOK, DMODEL, DMODEL);

    // 3) attention (tensor core) -> ctx hi/lo
    dim3 gAttn(SEQ/64, BATCH*NHEAD);
    attn_mma<<<gAttn, 128, ATT_SMEM>>>(p_qh, p_ql, p_kh, p_kl, p_vth, p_vtl,
                                       p_ctxh, p_ctxl);

    // 4) out projection + bias + residual(x) -> res1 (fp32)
    gemm_mma<3><<<g1024, 256, GEMM_SMEM>>>(p_ctxh, p_ctxl, p_woh, p_wol,
                                           b_out, x, p_res1, nullptr, nullptr,
                                           MTOK, DMODEL, DMODEL);

    // 5) LN2 -> hi/lo
    ln_hl_kernel<<<MTOK, 256>>>(p_res1, ln2_scale, ln2_shift, p_ln2h, p_ln2l);

    // 6) FFN1 + bias + gelu -> h1 hi/lo
    gemm_mma<2><<<g4096, 256, GEMM_SMEM>>>(p_ln2h, p_ln2l, p_w1h, p_w1l,
                                           b1, nullptr, nullptr, p_h1h, p_h1l,
                                           MTOK, FFN, DMODEL);

    // 7) FFN2 + bias + residual(res1) -> out
    gemm_mma<3><<<g1024, 256, GEMM_SMEM>>>(p_h1h, p_h1l, p_w2h, p_w2l,
                                           b2, p_res1, out, nullptr, nullptr,
                                           MTOK, DMODEL, FFN);

    (void)in_sizes; (void)n_in; (void)out_size;
}

// round 7
// speedup vs baseline: 4.0198x; 1.0057x over previous
#include <cuda_runtime.h>
#include <cuda_bf16.h>
#include <math.h>
#include <float.h>
#include <stdint.h>

// Problem dims (fixed)
#define BATCH 2
#define SEQ   2048
#define DMODEL 1024
#define NHEAD 16
#define HDIM  64
#define FFN   4096
#define MTOK  (BATCH*SEQ)          // 4096 token rows
#define SEGSZ ((size_t)MTOK*DMODEL)

typedef __nv_bfloat16 bf16;

// ---------------- scratch (allocation-free: __device__ globals) ----------------
__device__ float g_res1[MTOK*DMODEL];

__device__ bf16 g_ln1_hi[MTOK*DMODEL], g_ln1_lo[MTOK*DMODEL];
// fused QKV activations: [Q tok-major | K tok-major | V head-transposed]
__device__ bf16 g_qkv_hi[3*MTOK*DMODEL], g_qkv_lo[3*MTOK*DMODEL];
__device__ bf16 g_ctx_hi[MTOK*DMODEL], g_ctx_lo[MTOK*DMODEL];
__device__ bf16 g_ln2_hi[MTOK*DMODEL], g_ln2_lo[MTOK*DMODEL];
__device__ bf16 g_h1_hi [MTOK*FFN],    g_h1_lo [MTOK*FFN];

__device__ bf16 g_wqkvT_hi[3*DMODEL*DMODEL], g_wqkvT_lo[3*DMODEL*DMODEL];
__device__ bf16 g_woT_hi[DMODEL*DMODEL],     g_woT_lo[DMODEL*DMODEL];
__device__ bf16 g_w1T_hi[DMODEL*FFN],        g_w1T_lo[DMODEL*FFN];
__device__ bf16 g_w2T_hi[FFN*DMODEL],        g_w2T_lo[FFN*DMODEL];

// ---------------- PTX helpers (baseline compute_103-safe: sm_80-era ops only) ----
__device__ __forceinline__ uint32_t smem_u32(const void* p) {
    uint32_t a;
    asm("{ .reg .u64 t; cvta.to.shared.u64 t, %1; cvt.u32.u64 %0, t; }" : "=r"(a) : "l"(p));
    return a;
}
__device__ __forceinline__ void cpa16(uint32_t dst, const void* src) {
    asm volatile("cp.async.cg.shared.global [%0], [%1], 16;" :: "r"(dst), "l"(src));
}
__device__ __forceinline__ void cpa_commit() { asm volatile("cp.async.commit_group;"); }
__device__ __forceinline__ void cpa_wait2()  { asm volatile("cp.async.wait_group 2;" ::: "memory"); }
__device__ __forceinline__ void cpa_wait1()  { asm volatile("cp.async.wait_group 1;" ::: "memory"); }
__device__ __forceinline__ void cpa_wait0()  { asm volatile("cp.async.wait_group 0;" ::: "memory"); }

#define LDSM4(r, a) \
    asm volatile("ldmatrix.sync.aligned.m8n8.x4.shared.b16 {%0,%1,%2,%3}, [%4];" \
        : "=r"((r)[0]), "=r"((r)[1]), "=r"((r)[2]), "=r"((r)[3]) : "r"(a))

#define MMA_BF16(d, a, b0, b1) \
    asm volatile("mma.sync.aligned.m16n8k16.row.col.f32.bf16.bf16.f32 " \
        "{%0,%1,%2,%3}, {%4,%5,%6,%7}, {%8,%9}, {%0,%1,%2,%3};" \
        : "+f"((d)[0]), "+f"((d)[1]), "+f"((d)[2]), "+f"((d)[3]) \
        : "r"((a)[0]), "r"((a)[1]), "r"((a)[2]), "r"((a)[3]), "r"(b0), "r"(b1))

__device__ __forceinline__ float gelu_tanh(float x) {
    const float c = 0.7978845608028654f;
    float t = c * (x + 0.044715f * x * x * x);
    return 0.5f * x * (1.0f + tanhf(t));
}
__device__ __forceinline__ void split_hl(float v, bf16& h, bf16& l) {
    h = __float2bfloat16(v);
    l = __float2bfloat16(v - __bfloat162float(h));
}
__device__ __forceinline__ uint32_t pk2(float x, float y) {
    __nv_bfloat162 t;
    t.x = __float2bfloat16(x);
    t.y = __float2bfloat16(y);
    return *(uint32_t*)&t;
}

// ---------------- LayerNorm -> hi/lo bf16 (torch var ddof=1) ----------------
__global__ __launch_bounds__(256)
void ln_hl_kernel(const float* __restrict__ x, const float* __restrict__ sc,
                  const float* __restrict__ sh, bf16* __restrict__ ohi, bf16* __restrict__ olo)
{
    int row = blockIdx.x;
    int tid = threadIdx.x;
    const float4 a = *(const float4*)&x[(size_t)row * DMODEL + tid * 4];

    float s = a.x + a.y + a.z + a.w;
    float q = a.x*a.x + a.y*a.y + a.z*a.z + a.w*a.w;
    #pragma unroll
    for (int off = 16; off > 0; off >>= 1) {
        s += __shfl_xor_sync(0xFFFFFFFFu, s, off);
        q += __shfl_xor_sync(0xFFFFFFFFu, q, off);
    }
    __shared__ float reds[8], redq[8], stats[2];
    int wid = tid >> 5, lane = tid & 31;
    if (lane == 0) { reds[wid] = s; redq[wid] = q; }
    __syncthreads();
    if (tid == 0) {
        float S = 0.f, Q = 0.f;
        #pragma unroll
        for (int i = 0; i < 8; i++) { S += reds[i]; Q += redq[i]; }
        float mean = S * (1.0f / DMODEL);
        float var  = (Q - S * mean) * (1.0f / (DMODEL - 1));
        stats[0] = mean;
        stats[1] = rsqrtf(var + 1e-5f);
    }
    __syncthreads();
    float mean = stats[0], rstd = stats[1];
    const float4 scv = *(const float4*)&sc[tid * 4];
    const float4 shv = *(const float4*)&sh[tid * 4];
    float o[4];
    o[0] = (a.x - mean) * rstd * scv.x + shv.x;
    o[1] = (a.y - mean) * rstd * scv.y + shv.y;
    o[2] = (a.z - mean) * rstd * scv.z + shv.z;
    o[3] = (a.w - mean) * rstd * scv.w + shv.w;

    union { bf16 b[4]; uint2 u; } uh, ul;
    #pragma unroll
    for (int i = 0; i < 4; i++) split_hl(o[i], uh.b[i], ul.b[i]);
    size_t idx = (size_t)row * DMODEL + tid * 4;
    *(uint2*)&ohi[idx] = uh.u;
    *(uint2*)&olo[idx] = ul.u;
}

// ---------------- weight transpose+convert: W[K,N] f32 -> WT hi/lo bf16 [N,K] ----------------
__global__ __launch_bounds__(256)
void wconvT(const float* __restrict__ W, bf16* __restrict__ ThT, bf16* __restrict__ TlT,
            int K, int N)
{
    __shared__ float t[32][33];
    int tx = threadIdx.x & 31, ty = threadIdx.x >> 5;
    int k0 = blockIdx.y * 32, n0 = blockIdx.x * 32;
    #pragma unroll
    for (int j = 0; j < 4; j++)
        t[ty + j * 8][tx] = W[(size_t)(k0 + ty + j * 8) * N + n0 + tx];
    __syncthreads();
    #pragma unroll
    for (int j = 0; j < 4; j++) {
        int n = n0 + ty + j * 8;
        float v = t[tx][ty + j * 8];
        bf16 h, l; split_hl(v, h, l);
        ThT[(size_t)n * K + k0 + tx] = h;
        TlT[(size_t)n * K + k0 + tx] = l;
    }
}

// batched: wq/wk/wv -> fused qkvT buffer (z=0..2), wo -> woT (z=3); all 1024x1024
__global__ __launch_bounds__(256)
void wconv_qkvo(const float* __restrict__ wq, const float* __restrict__ wk,
                const float* __restrict__ wv, const float* __restrict__ wo,
                bf16* __restrict__ qkvh, bf16* __restrict__ qkvl,
                bf16* __restrict__ woh, bf16* __restrict__ wol)
{
    const int z = blockIdx.z;
    const float* W = (z == 0) ? wq : (z == 1) ? wk : (z == 2) ? wv : wo;
    bf16* Th = (z < 3) ? qkvh + (size_t)z * DMODEL * DMODEL : woh;
    bf16* Tl = (z < 3) ? qkvl + (size_t)z * DMODEL * DMODEL : wol;

    __shared__ float t[32][33];
    int tx = threadIdx.x & 31, ty = threadIdx.x >> 5;
    int k0 = blockIdx.y * 32, n0 = blockIdx.x * 32;
    #pragma unroll
    for (int j = 0; j < 4; j++)
        t[ty + j * 8][tx] = W[(size_t)(k0 + ty + j * 8) * DMODEL + n0 + tx];
    __syncthreads();
    #pragma unroll
    for (int j = 0; j < 4; j++) {
        int n = n0 + ty + j * 8;
        float v = t[tx][ty + j * 8];
        bf16 h, l; split_hl(v, h, l);
        Th[(size_t)n * DMODEL + k0 + tx] = h;
        Tl[(size_t)n * DMODEL + k0 + tx] = l;
    }
}

// ---------------- mma.sync bf16x3 GEMM: C[M,N] = A[M,K] @ B^T (B given as [N,K]) --
// CTA 128x128, BK=64, 256 threads, warp grid 2(M)x4(N), warp tile 64x32. 3-stage cp.async.
// EPI: 2 = +bias,gelu -> hi/lo bf16; 3 = +bias +res -> fp32;
//      5 = fused QKV routing (seg0 Q, seg1 K tok-major; seg2 V head-transposed)
#define TILE_BYTES 16384
#define STAGE_BYTES (4*TILE_BYTES)
#define GEMM_SMEM   (3*STAGE_BYTES)      // 196608

template<int EPI>
__global__ __launch_bounds__(256, 1)
void gemm_mma(const bf16* __restrict__ Ahi, const bf16* __restrict__ Alo,
              const bf16* __restrict__ Bhi, const bf16* __restrict__ Blo,
              const float* __restrict__ bias, const float* __restrict__ res,
              float* __restrict__ Cf, bf16* __restrict__ Chi, bf16* __restrict__ Clo,
              int M, int N, int K)
{
    extern __shared__ char smem[];
    const uint32_t sbase = smem_u32(smem);
    const int tid  = threadIdx.x;
    const int wid  = tid >> 5, lane = tid & 31;
    const int m0 = blockIdx.y * 128, n0 = blockIdx.x * 128;
    const int wm = (wid & 1) * 64, wn = (wid >> 1) * 32;

    const bf16* srcs[4];
    srcs[0] = Ahi + (size_t)m0 * K;
    srcs[1] = Alo + (size_t)m0 * K;
    srcs[2] = Bhi + (size_t)n0 * K;
    srcs[3] = Blo + (size_t)n0 * K;

    float acc[4][4][4];
    #pragma unroll
    for (int a = 0; a < 4; a++)
        #pragma unroll
        for (int b = 0; b < 4; b++)
            #pragma unroll
            for (int c = 0; c < 4; c++) acc[a][b][c] = 0.f;

    const int NC = K >> 6;

    auto load_stage = [&](int chunk, int stage) {
        const int k0 = chunk << 6;
        const uint32_t base = sbase + stage * STAGE_BYTES;
        #pragma unroll
        for (int j = 0; j < 16; j++) {
            const int tile = j >> 2;
            const int cid  = ((j & 3) << 8) + tid;
            const int row  = cid >> 3;
            const int c    = cid & 7;
            uint32_t dst = base + tile * TILE_BYTES + row * 128 + ((c ^ (row & 7)) << 4);
            cpa16(dst, srcs[tile] + (size_t)row * K + k0 + c * 8);
        }
        cpa_commit();
    };

    load_stage(0, 0);
    load_stage(1, 1);
    load_stage(2, 2);

    for (int i = 0; i < NC; i++) {
        const int rem = NC - 1 - i;
        if (rem >= 2) cpa_wait2(); else if (rem == 1) cpa_wait1(); else cpa_wait0();
        __syncthreads();
        const uint32_t tb = sbase + (i % 3) * STAGE_BYTES;

        #pragma unroll
        for (int ks = 0; ks < 4; ks++) {
            uint32_t ah[4][4], al[4][4], bh[2][4], bl[2][4];
            #pragma unroll
            for (int mt = 0; mt < 4; mt++) {
                int row = wm + mt * 16 + (lane & 15);
                int kg  = ks * 2 + (lane >> 4);
                uint32_t off = row * 128 + ((kg ^ (row & 7)) << 4);
                LDSM4(ah[mt], tb + off);
                LDSM4(al[mt], tb + TILE_BYTES + off);
            }
            #pragma unroll
            for (int bt = 0; bt < 2; bt++) {
                int row = wn + bt * 16 + ((lane >> 4) << 3) + (lane & 7);
                int kg  = ks * 2 + ((lane >> 3) & 1);
                uint32_t off = row * 128 + ((kg ^ (row & 7)) << 4);
                LDSM4(bh[bt], tb + 2 * TILE_BYTES + off);
                LDSM4(bl[bt], tb + 3 * TILE_BYTES + off);
            }
            #pragma unroll
            for (int mt = 0; mt < 4; mt++)
                #pragma unroll
                for (int nt = 0; nt < 4; nt++) {
                    uint32_t b0h = bh[nt >> 1][(nt & 1) * 2], b1h = bh[nt >> 1][(nt & 1) * 2 + 1];
                    uint32_t b0l = bl[nt >> 1][(nt & 1) * 2], b1l = bl[nt >> 1][(nt & 1) * 2 + 1];
                    MMA_BF16(acc[mt][nt], ah[mt], b0h, b1h);
                    MMA_BF16(acc[mt][nt], ah[mt], b0l, b1l);
                    MMA_BF16(acc[mt][nt], al[mt], b0h, b1h);
                }
        }
        __syncthreads();
        if (i + 3 < NC) load_stage(i + 3, i % 3);
    }

    // ---- epilogue (fragment: rows g, g+8; cols 2t, 2t+1) ----
    const int g = lane >> 2, t = lane & 3;
    #pragma unroll
    for (int mt = 0; mt < 4; mt++) {
        #pragma unroll
        for (int nt = 0; nt < 4; nt++) {
            const int gr0 = m0 + wm + mt * 16 + g;
            const int gr1 = gr0 + 8;
            const int gc  = n0 + wn + nt * 8 + 2 * t;
            float v00 = acc[mt][nt][0], v01 = acc[mt][nt][1];
            float v10 = acc[mt][nt][2], v11 = acc[mt][nt][3];
            if (EPI == 3) {
                const float2 bv  = *(const float2*)&bias[gc];
                const float2 r0v = *(const float2*)&res[(size_t)gr0 * N + gc];
                const float2 r1v = *(const float2*)&res[(size_t)gr1 * N + gc];
                *(float2*)&Cf[(size_t)gr0 * N + gc] =
                    make_float2(v00 + bv.x + r0v.x, v01 + bv.y + r0v.y);
                *(float2*)&Cf[(size_t)gr1 * N + gc] =
                    make_float2(v10 + bv.x + r1v.x, v11 + bv.y + r1v.y);
            } else if (EPI == 2) {
                const float2 bv = *(const float2*)&bias[gc];
                float x00 = gelu_tanh(v00 + bv.x), x01 = gelu_tanh(v01 + bv.y);
                float x10 = gelu_tanh(v10 + bv.x), x11 = gelu_tanh(v11 + bv.y);
                __nv_bfloat162 h0, l0, h1, l1;
                split_hl(x00, h0.x, l0.x); split_hl(x01, h0.y, l0.y);
                split_hl(x10, h1.x, l1.x); split_hl(x11, h1.y, l1.y);
                *(__nv_bfloat162*)&Chi[(size_t)gr0 * N + gc] = h0;
                *(__nv_bfloat162*)&Clo[(size_t)gr0 * N + gc] = l0;
                *(__nv_bfloat162*)&Chi[(size_t)gr1 * N + gc] = h1;
                *(__nv_bfloat162*)&Clo[(size_t)gr1 * N + gc] = l1;
            } else { // EPI == 5: fused QKV
                const int seg = gc >> 10;       // constant per CTA (n0 mult of 128)
                const int col = gc & 1023;
                if (seg < 2) {
                    const size_t base = (size_t)seg * SEGSZ;
                    __nv_bfloat162 h0, l0, h1, l1;
                    split_hl(v00, h0.x, l0.x); split_hl(v01, h0.y, l0.y);
                    split_hl(v10, h1.x, l1.x); split_hl(v11, h1.y, l1.y);
                    *(__nv_bfloat162*)&Chi[base + (size_t)gr0 * DMODEL + col] = h0;
                    *(__nv_bfloat162*)&Clo[base + (size_t)gr0 * DMODEL + col] = l0;
                    *(__nv_bfloat162*)&Chi[base + (size_t)gr1 * DMODEL + col] = h1;
                    *(__nv_bfloat162*)&Clo[base + (size_t)gr1 * DMODEL + col] = l1;
                } else {    // V head-transposed: [b*16+h][d][s]
                    #pragma unroll
                    for (int e = 0; e < 4; e++) {
                        int gr = (e < 2) ? gr0 : gr1;
                        int cc = col + (e & 1);
                        float v = (e == 0) ? v00 : (e == 1) ? v01 : (e == 2) ? v10 : v11;
                        int b = gr >> 11, s = gr & 2047;
                        int h = cc >> 6, d = cc & 63;
                        size_t o = 2 * SEGSZ + ((size_t)((b * 16 + h) * 64 + d)) * 2048 + s;
                        bf16 hh, ll; split_hl(v, hh, ll);
                        Chi[o] = hh;
                        Clo[o] = ll;
                    }
                }
            }
        }
    }
}

// ---------------- mma.sync flash attention (bf16x3, causal) -> ctx hi/lo ----------
// CTA: 128 q-rows x one (b,h). 256 threads = 8 warps x 16 rows. KV tile = 64 keys.
// smem: Qhi@0 (16KB), Qlo@16384; stage s @32768+s*32768: Khi,Klo,Vhi,Vlo (8KB each)
#define ATT_SMEM (32768 + 2*32768)

__global__ __launch_bounds__(256, 1)
void attn_mma(const bf16* __restrict__ qhi, const bf16* __restrict__ qlo,
              const bf16* __restrict__ khi, const bf16* __restrict__ klo,
              const bf16* __restrict__ vthi, const bf16* __restrict__ vtlo,
              bf16* __restrict__ chi, bf16* __restrict__ clo)
{
    extern __shared__ char smem[];
    const uint32_t sbase = smem_u32(smem);
    const int tid  = threadIdx.x;
    const int wid  = tid >> 5, lane = tid & 31;
    const int g = lane >> 2, t = lane & 3;
    const int bh = blockIdx.y;
    const int b = bh >> 4, h = bh & 15;
    const int m0 = (gridDim.x - 1 - blockIdx.x) * 128;   // longest blocks first
    const int nit = m0 / 64 + 2;

    // ---- load Q tile (128 rows, hi/lo) ----
    {
        const bf16* qs[2] = { qhi + ((size_t)(b * SEQ + m0)) * DMODEL + h * 64,
                              qlo + ((size_t)(b * SEQ + m0)) * DMODEL + h * 64 };
        #pragma unroll
        for (int tl = 0; tl < 2; tl++)
            #pragma unroll
            for (int j = 0; j < 4; j++) {
                int cid = j * 256 + tid;          // 0..1023
                int row = cid >> 3, c = cid & 7;
                cpa16(sbase + tl * 16384 + row * 128 + ((c ^ (row & 7)) << 4),
                      qs[tl] + (size_t)row * DMODEL + c * 8);
            }
        cpa_commit();
    }

    auto load_kv = [&](int it, int stage) {
        const int n0 = it * 64;
        const uint32_t base = sbase + 32768 + stage * 32768;
        const bf16* ks_[2] = { khi + ((size_t)(b * SEQ + n0)) * DMODEL + h * 64,
                               klo + ((size_t)(b * SEQ + n0)) * DMODEL + h * 64 };
        const bf16* vs_[2] = { vthi + ((size_t)(bh * 64)) * 2048 + n0,
                               vtlo + ((size_t)(bh * 64)) * 2048 + n0 };
        #pragma unroll
        for (int tl = 0; tl < 2; tl++)
            #pragma unroll
            for (int j = 0; j < 2; j++) {
                int cid = j * 256 + tid;          // 0..511
                int row = cid >> 3, c = cid & 7;
                uint32_t sw = row * 128 + ((c ^ (row & 7)) << 4);
                cpa16(base + tl * 8192 + sw,         ks_[tl] + (size_t)row * DMODEL + c * 8);
                cpa16(base + 16384 + tl * 8192 + sw, vs_[tl] + (size_t)row * 2048 + c * 8);
            }
        cpa_commit();
    };

    load_kv(0, 0);
    load_kv(1, 1);

    // Q fragments (constant across iters)
    cpa_wait2();
    __syncthreads();
    uint32_t qh[4][4], ql[4][4];
    #pragma unroll
    for (int ks = 0; ks < 4; ks++) {
        int row = wid * 16 + (lane & 15);
        int kg  = ks * 2 + (lane >> 4);
        uint32_t off = row * 128 + ((kg ^ (row & 7)) << 4);
        LDSM4(qh[ks], sbase + off);
        LDSM4(ql[ks], sbase + 16384 + off);
    }

    float m[2] = { -INFINITY, -INFINITY };
    float l[2] = { 0.f, 0.f };
    float acc_o[8][4];
    #pragma unroll
    for (int i = 0; i < 8; i++)
        #pragma unroll
        for (int c = 0; c < 4; c++) acc_o[i][c] = 0.f;

    const int rowL64 = (wid & 3) * 16 + g;        // row within own 64-block
    const int wdiag  = (wid < 4) ? (nit - 2) : (nit - 1);

    for (int it = 0; it < nit; it++) {
        const int rem = nit - 1 - it;
        if (rem >= 1) cpa_wait1(); else cpa_wait0();
        __syncthreads();
        const uint32_t kb = sbase + 32768 + (it & 1) * 32768;
        const uint32_t vb = kb + 16384;
        const bool active = !(wid < 4 && it == nit - 1);   // warps 0-3 skip final block

        if (active) {
            const bool diag = (it == wdiag);

            // ---- S = Q K^T (bf16x3) ----
            float s[8][4];
            #pragma unroll
            for (int i = 0; i < 8; i++)
                #pragma unroll
                for (int c = 0; c < 4; c++) s[i][c] = 0.f;

            #pragma unroll
            for (int ks = 0; ks < 4; ks++) {
                uint32_t kh[4][4], kl[4][4];
                #pragma unroll
                for (int bt = 0; bt < 4; bt++) {
                    int row = bt * 16 + ((lane >> 4) << 3) + (lane & 7);
                    int kg  = ks * 2 + ((lane >> 3) & 1);
                    uint32_t off = row * 128 + ((kg ^ (row & 7)) << 4);
                    LDSM4(kh[bt], kb + off);
                    LDSM4(kl[bt], kb + 8192 + off);
                }
                #pragma unroll
                for (int nt = 0; nt < 8; nt++) {
                    uint32_t b0h = kh[nt >> 1][(nt & 1) * 2], b1h = kh[nt >> 1][(nt & 1) * 2 + 1];
                    uint32_t b0l = kl[nt >> 1][(nt & 1) * 2], b1l = kl[nt >> 1][(nt & 1) * 2 + 1];
                    MMA_BF16(s[nt], qh[ks], b0h, b1h);
                    MMA_BF16(s[nt], qh[ks], b0l, b1l);
                    MMA_BF16(s[nt], ql[ks], b0h, b1h);
                }
            }

            // ---- scale + causal mask + online softmax ----
            #pragma unroll
            for (int nt = 0; nt < 8; nt++) {
                #pragma unroll
                for (int c = 0; c < 4; c++) {
                    int colL = nt * 8 + 2 * t + (c & 1);
                    int rowL = rowL64 + ((c >> 1) << 3);
                    float v = s[nt][c] * 0.125f;
                    if (diag && colL > rowL) v = -INFINITY;
                    s[nt][c] = v;
                }
            }
            float mx0 = -INFINITY, mx1 = -INFINITY;
            #pragma unroll
            for (int nt = 0; nt < 8; nt++) {
                mx0 = fmaxf(mx0, fmaxf(s[nt][0], s[nt][1]));
                mx1 = fmaxf(mx1, fmaxf(s[nt][2], s[nt][3]));
            }
            mx0 = fmaxf(mx0, __shfl_xor_sync(0xFFFFFFFFu, mx0, 1));
            mx0 = fmaxf(mx0, __shfl_xor_sync(0xFFFFFFFFu, mx0, 2));
            mx1 = fmaxf(mx1, __shfl_xor_sync(0xFFFFFFFFu, mx1, 1));
            mx1 = fmaxf(mx1, __shfl_xor_sync(0xFFFFFFFFu, mx1, 2));
            float mn0 = fmaxf(m[0], mx0), mn1 = fmaxf(m[1], mx1);
            float a0 = __expf(m[0] - mn0), a1 = __expf(m[1] - mn1);
            m[0] = mn0; m[1] = mn1;
            #pragma unroll
            for (int i = 0; i < 8; i++) {
                acc_o[i][0] *= a0; acc_o[i][1] *= a0;
                acc_o[i][2] *= a1; acc_o[i][3] *= a1;
            }
            float sum0 = 0.f, sum1 = 0.f;
            float p[8][4];
            #pragma unroll
            for (int nt = 0; nt < 8; nt++) {
                p[nt][0] = __expf(s[nt][0] - mn0); p[nt][1] = __expf(s[nt][1] - mn0);
                p[nt][2] = __expf(s[nt][2] - mn1); p[nt][3] = __expf(s[nt][3] - mn1);
                sum0 += p[nt][0] + p[nt][1];
                sum1 += p[nt][2] + p[nt][3];
            }
            sum0 += __shfl_xor_sync(0xFFFFFFFFu, sum0, 1);
            sum0 += __shfl_xor_sync(0xFFFFFFFFu, sum0, 2);
            sum1 += __shfl_xor_sync(0xFFFFFFFFu, sum1, 1);
            sum1 += __shfl_xor_sync(0xFFFFFFFFu, sum1, 2);
            l[0] = l[0] * a0 + sum0;
            l[1] = l[1] * a1 + sum1;

            // ---- O += P V (bf16x3); P split hi/lo in-register ----
            #pragma unroll
            for (int ks2 = 0; ks2 < 4; ks2++) {
                float ph[8], pl[8];
                #pragma unroll
                for (int e = 0; e < 2; e++) {
                    int nt = 2 * ks2 + e;
                    #pragma unroll
                    for (int c = 0; c < 4; c++) {
                        bf16 hh, ll; split_hl(p[nt][c], hh, ll);
                        ph[e * 4 + c] = __bfloat162float(hh);
                        pl[e * 4 + c] = p[nt][c] - ph[e * 4 + c];
                    }
                }
                uint32_t pah[4], pal[4];
                pah[0] = pk2(ph[0], ph[1]); pah[1] = pk2(ph[2], ph[3]);
                pah[2] = pk2(ph[4], ph[5]); pah[3] = pk2(ph[6], ph[7]);
                pal[0] = pk2(pl[0], pl[1]); pal[1] = pk2(pl[2], pl[3]);
                pal[2] = pk2(pl[4], pl[5]); pal[3] = pk2(pl[6], pl[7]);

                uint32_t vh[4][4], vl[4][4];
                #pragma unroll
                for (int dt = 0; dt < 4; dt++) {
                    int row = dt * 16 + ((lane >> 4) << 3) + (lane & 7);
                    int kg  = ks2 * 2 + ((lane >> 3) & 1);
                    uint32_t off = row * 128 + ((kg ^ (row & 7)) << 4);
                    LDSM4(vh[dt], vb + off);
                    LDSM4(vl[dt], vb + 8192 + off);
                }
                #pragma unroll
                for (int nt = 0; nt < 8; nt++) {
                    uint32_t b0h = vh[nt >> 1][(nt & 1) * 2], b1h = vh[nt >> 1][(nt & 1) * 2 + 1];
                    uint32_t b0l = vl[nt >> 1][(nt & 1) * 2], b1l = vl[nt >> 1][(nt & 1) * 2 + 1];
                    MMA_BF16(acc_o[nt], pah, b0h, b1h);
                    MMA_BF16(acc_o[nt], pah, b0l, b1l);
                    MMA_BF16(acc_o[nt], pal, b0h, b1h);
                }
            }
        }

        __syncthreads();
        if (it + 2 < nit) load_kv(it + 2, it & 1);
    }

    // ---- epilogue ----
    float inv0 = 1.0f / l[0], inv1 = 1.0f / l[1];
    const size_t gr0 = (size_t)(b * SEQ + m0 + wid * 16 + g) * DMODEL + h * 64;
    const size_t gr1 = gr0 + 8 * DMODEL;
    #pragma unroll
    for (int nt = 0; nt < 8; nt++) {
        int gc = nt * 8 + 2 * t;
        __nv_bfloat162 h0, l0h, h1, l1h;
        split_hl(acc_o[nt][0] * inv0, h0.x, l0h.x);
        split_hl(acc_o[nt][1] * inv0, h0.y, l0h.y);
        split_hl(acc_o[nt][2] * inv1, h1.x, l1h.x);
        split_hl(acc_o[nt][3] * inv1, h1.y, l1h.y);
        *(__nv_bfloat162*)&chi[gr0 + gc] = h0;
        *(__nv_bfloat162*)&clo[gr0 + gc] = l0h;
        *(__nv_bfloat162*)&chi[gr1 + gc] = h1;
        *(__nv_bfloat162*)&clo[gr1 + gc] = l1h;
    }
}

// ---------------- launch ----------------
extern "C" void kernel_launch(void* const* d_in, const int* in_sizes, int n_in,
                              void* d_out, int out_size)
{
    const float* x         = (const float*)d_in[0];
    const float* ln1_scale = (const float*)d_in[1];
    const float* ln1_shift = (const float*)d_in[2];
    const float* wq        = (const float*)d_in[3];
    const float* wk        = (const float*)d_in[4];
    const float* wv        = (const float*)d_in[5];
    const float* w_out     = (const float*)d_in[6];
    const float* b_out     = (const float*)d_in[7];
    const float* ln2_scale = (const float*)d_in[8];
    const float* ln2_shift = (const float*)d_in[9];
    const float* w1        = (const float*)d_in[10];
    const float* b1        = (const float*)d_in[11];
    const float* w2        = (const float*)d_in[12];
    const float* b2        = (const float*)d_in[13];
    float* out = (float*)d_out;

    float *p_res1;
    bf16 *p_ln1h, *p_ln1l, *p_qkvh, *p_qkvl;
    bf16 *p_ctxh, *p_ctxl, *p_ln2h, *p_ln2l, *p_h1h, *p_h1l;
    bf16 *p_wqkvh, *p_wqkvl, *p_woh, *p_wol, *p_w1h, *p_w1l, *p_w2h, *p_w2l;
    cudaGetSymbolAddress((void**)&p_res1,  g_res1);
    cudaGetSymbolAddress((void**)&p_ln1h,  g_ln1_hi);
    cudaGetSymbolAddress((void**)&p_ln1l,  g_ln1_lo);
    cudaGetSymbolAddress((void**)&p_qkvh,  g_qkv_hi);
    cudaGetSymbolAddress((void**)&p_qkvl,  g_qkv_lo);
    cudaGetSymbolAddress((void**)&p_ctxh,  g_ctx_hi);
    cudaGetSymbolAddress((void**)&p_ctxl,  g_ctx_lo);
    cudaGetSymbolAddress((void**)&p_ln2h,  g_ln2_hi);
    cudaGetSymbolAddress((void**)&p_ln2l,  g_ln2_lo);
    cudaGetSymbolAddress((void**)&p_h1h,   g_h1_hi);
    cudaGetSymbolAddress((void**)&p_h1l,   g_h1_lo);
    cudaGetSymbolAddress((void**)&p_wqkvh, g_wqkvT_hi);
    cudaGetSymbolAddress((void**)&p_wqkvl, g_wqkvT_lo);
    cudaGetSymbolAddress((void**)&p_woh,   g_woT_hi);
    cudaGetSymbolAddress((void**)&p_wol,   g_woT_lo);
    cudaGetSymbolAddress((void**)&p_w1h,   g_w1T_hi);
    cudaGetSymbolAddress((void**)&p_w1l,   g_w1T_lo);
    cudaGetSymbolAddress((void**)&p_w2h,   g_w2T_hi);
    cudaGetSymbolAddress((void**)&p_w2l,   g_w2T_lo);

    static bool attr_set = false;
    if (!attr_set) {
        cudaFuncSetAttribute(attn_mma,    cudaFuncAttributeMaxDynamicSharedMemorySize, ATT_SMEM);
        cudaFuncSetAttribute(gemm_mma<2>, cudaFuncAttributeMaxDynamicSharedMemorySize, GEMM_SMEM);
        cudaFuncSetAttribute(gemm_mma<3>, cudaFuncAttributeMaxDynamicSharedMemorySize, GEMM_SMEM);
        cudaFuncSetAttribute(gemm_mma<5>, cudaFuncAttributeMaxDynamicSharedMemorySize, GEMM_SMEM);
        attr_set = true;
    }

    // 0) weight transpose + hi/lo convert
    wconv_qkvo<<<dim3(DMODEL/32, DMODEL/32, 4), 256>>>(wq, wk, wv, w_out,
                                                       p_wqkvh, p_wqkvl, p_woh, p_wol);
    wconvT<<<dim3(FFN/32,    DMODEL/32), 256>>>(w1, p_w1h, p_w1l, DMODEL, FFN);
    wconvT<<<dim3(DMODEL/32, FFN/32),    256>>>(w2, p_w2h, p_w2l, FFN,    DMODEL);

    // 1) LN1 -> hi/lo
    ln_hl_kernel<<<MTOK, 256>>>(x, ln1_scale, ln1_shift, p_ln1h, p_ln1l);

    dim3 gQKV(3*DMODEL/128, MTOK/128);  // (24, 32)
    dim3 g1024(DMODEL/128,  MTOK/128);  // (8, 32)
    dim3 g4096(FFN/128,     MTOK/128);  // (32, 32)

    // 2) fused QKV projection -> hi/lo bf16 (V head-transposed)
    gemm_mma<5><<<gQKV, 256, GEMM_SMEM>>>(p_ln1h, p_ln1l, p_wqkvh, p_wqkvl,
                                          nullptr, nullptr, nullptr, p_qkvh, p_qkvl,
                                          MTOK, 3*DMODEL, DMODEL);

    // 3) attention (tensor core) -> ctx hi/lo
    dim3 gAttn(SEQ/128, BATCH*NHEAD);   // (16, 32)
    attn_mma<<<gAttn, 256, ATT_SMEM>>>(p_qkvh,            p_qkvl,
                                       p_qkvh + SEGSZ,    p_qkvl + SEGSZ,
                                       p_qkvh + 2*SEGSZ,  p_qkvl + 2*SEGSZ,
                                       p_ctxh, p_ctxl);

    // 4) out projection + bias + residual(x) -> res1 (fp32)
    gemm_mma<3><<<g1024, 256, GEMM_SMEM>>>(p_ctxh, p_ctxl, p_woh, p_wol,
                                           b_out, x, p_res1, nullptr, nullptr,
                                           MTOK, DMODEL, DMODEL);

    // 5) LN2 -> hi/lo
    ln_hl_kernel<<<MTOK, 256>>>(p_res1, ln2_scale, ln2_shift, p_ln2h, p_ln2l);

    // 6) FFN1 + bias + gelu -> h1 hi/lo
    gemm_mma<2><<<g4096, 256, GEMM_SMEM>>>(p_ln2h, p_ln2l, p_w1h, p_w1l,
                                           b1, nullptr, nullptr, p_h1h, p_h1l,
                                           MTOK, FFN, DMODEL);

    // 7) FFN2 + bias + residual(res1) -> out
    gemm_mma<3><<<g1024, 256, GEMM_SMEM>>>(p_h1h, p_h1l, p_w2h, p_w2l,
                                           b2, p_res1, out, nullptr, nullptr,
                                           MTOK, DMODEL, FFN);

    (void)in_sizes; (void)n_in; (void)out_size;
}

// round 11
// speedup vs baseline: 4.0306x; 1.0027x over previous
#include <cuda_runtime.h>
#include <cuda_bf16.h>
#include <math.h>
#include <float.h>
#include <stdint.h>

// Problem dims (fixed)
#define BATCH 2
#define SEQ   2048
#define DMODEL 1024
#define NHEAD 16
#define HDIM  64
#define FFN   4096
#define MTOK  (BATCH*SEQ)          // 4096 token rows
#define SEGSZ ((size_t)MTOK*DMODEL)

typedef __nv_bfloat16 bf16;

// ---------------- scratch (allocation-free: __device__ globals) ----------------
__device__ float g_res1[MTOK*DMODEL];

__device__ bf16 g_ln1_hi[MTOK*DMODEL], g_ln1_lo[MTOK*DMODEL];
// fused QKV activations: [Q(pre-scaled 1/8) tok-major | K tok-major | V head-transposed]
__device__ bf16 g_qkv_hi[3*MTOK*DMODEL], g_qkv_lo[3*MTOK*DMODEL];
__device__ bf16 g_ctx_hi[MTOK*DMODEL], g_ctx_lo[MTOK*DMODEL];
__device__ bf16 g_ln2_hi[MTOK*DMODEL], g_ln2_lo[MTOK*DMODEL];
__device__ bf16 g_h1_hi [MTOK*FFN],    g_h1_lo [MTOK*FFN];

__device__ bf16 g_wqkvT_hi[3*DMODEL*DMODEL], g_wqkvT_lo[3*DMODEL*DMODEL];
__device__ bf16 g_woT_hi[DMODEL*DMODEL],     g_woT_lo[DMODEL*DMODEL];
__device__ bf16 g_w1T_hi[DMODEL*FFN],        g_w1T_lo[DMODEL*FFN];
__device__ bf16 g_w2T_hi[FFN*DMODEL],        g_w2T_lo[FFN*DMODEL];

// ---------------- PTX helpers (baseline compute_103-safe: sm_80-era ops only) ----
__device__ __forceinline__ uint32_t smem_u32(const void* p) {
    uint32_t a;
    asm("{ .reg .u64 t; cvta.to.shared.u64 t, %1; cvt.u32.u64 %0, t; }" : "=r"(a) : "l"(p));
    return a;
}
__device__ __forceinline__ void cpa16(uint32_t dst, const void* src) {
    asm volatile("cp.async.cg.shared.global [%0], [%1], 16;" :: "r"(dst), "l"(src));
}
__device__ __forceinline__ void cpa_commit() { asm volatile("cp.async.commit_group;"); }
__device__ __forceinline__ void cpa_wait2()  { asm volatile("cp.async.wait_group 2;" ::: "memory"); }
__device__ __forceinline__ void cpa_wait1()  { asm volatile("cp.async.wait_group 1;" ::: "memory"); }
__device__ __forceinline__ void cpa_wait0()  { asm volatile("cp.async.wait_group 0;" ::: "memory"); }

#define LDSM4(r, a) \
    asm volatile("ldmatrix.sync.aligned.m8n8.x4.shared.b16 {%0,%1,%2,%3}, [%4];" \
        : "=r"((r)[0]), "=r"((r)[1]), "=r"((r)[2]), "=r"((r)[3]) : "r"(a))

#define MMA_BF16(d, a, b0, b1) \
    asm volatile("mma.sync.aligned.m16n8k16.row.col.f32.bf16.bf16.f32 " \
        "{%0,%1,%2,%3}, {%4,%5,%6,%7}, {%8,%9}, {%0,%1,%2,%3};" \
        : "+f"((d)[0]), "+f"((d)[1]), "+f"((d)[2]), "+f"((d)[3]) \
        : "r"((a)[0]), "r"((a)[1]), "r"((a)[2]), "r"((a)[3]), "r"(b0), "r"(b1))

__device__ __forceinline__ float gelu_tanh(float x) {
    const float c = 0.7978845608028654f;
    float t = c * (x + 0.044715f * x * x * x);
    return 0.5f * x * (1.0f + tanhf(t));
}
__device__ __forceinline__ void split_hl(float v, bf16& h, bf16& l) {
    h = __float2bfloat16(v);
    l = __float2bfloat16(v - __bfloat162float(h));
}
__device__ __forceinline__ uint32_t pk2(float x, float y) {
    __nv_bfloat162 t;
    t.x = __float2bfloat16(x);
    t.y = __float2bfloat16(y);
    return *(uint32_t*)&t;
}

// ---------------- LayerNorm -> hi/lo bf16 (torch var ddof=1) ----------------
__global__ __launch_bounds__(256)
void ln_hl_kernel(const float* __restrict__ x, const float* __restrict__ sc,
                  const float* __restrict__ sh, bf16* __restrict__ ohi, bf16* __restrict__ olo)
{
    int row = blockIdx.x;
    int tid = threadIdx.x;
    const float4 a = *(const float4*)&x[(size_t)row * DMODEL + tid * 4];

    float s = a.x + a.y + a.z + a.w;
    float q = a.x*a.x + a.y*a.y + a.z*a.z + a.w*a.w;
    #pragma unroll
    for (int off = 16; off > 0; off >>= 1) {
        s += __shfl_xor_sync(0xFFFFFFFFu, s, off);
        q += __shfl_xor_sync(0xFFFFFFFFu, q, off);
    }
    __shared__ float reds[8], redq[8], stats[2];
    int wid = tid >> 5, lane = tid & 31;
    if (lane == 0) { reds[wid] = s; redq[wid] = q; }
    __syncthreads();
    if (tid == 0) {
        float S = 0.f, Q = 0.f;
        #pragma unroll
        for (int i = 0; i < 8; i++) { S += reds[i]; Q += redq[i]; }
        float mean = S * (1.0f / DMODEL);
        float var  = (Q - S * mean) * (1.0f / (DMODEL - 1));
        stats[0] = mean;
        stats[1] = rsqrtf(var + 1e-5f);
    }
    __syncthreads();
    float mean = stats[0], rstd = stats[1];
    const float4 scv = *(const float4*)&sc[tid * 4];
    const float4 shv = *(const float4*)&sh[tid * 4];
    float o[4];
    o[0] = (a.x - mean) * rstd * scv.x + shv.x;
    o[1] = (a.y - mean) * rstd * scv.y + shv.y;
    o[2] = (a.z - mean) * rstd * scv.z + shv.z;
    o[3] = (a.w - mean) * rstd * scv.w + shv.w;

    union { bf16 b[4]; uint2 u; } uh, ul;
    #pragma unroll
    for (int i = 0; i < 4; i++) split_hl(o[i], uh.b[i], ul.b[i]);
    size_t idx = (size_t)row * DMODEL + tid * 4;
    *(uint2*)&ohi[idx] = uh.u;
    *(uint2*)&olo[idx] = ul.u;
}

// ---------------- weight transpose+convert: W[K,N] f32 -> WT hi/lo bf16 [N,K] ----------------
__global__ __launch_bounds__(256)
void wconvT(const float* __restrict__ W, bf16* __restrict__ ThT, bf16* __restrict__ TlT,
            int K, int N)
{
    __shared__ float t[32][33];
    int tx = threadIdx.x & 31, ty = threadIdx.x >> 5;
    int k0 = blockIdx.y * 32, n0 = blockIdx.x * 32;
    #pragma unroll
    for (int j = 0; j < 4; j++)
        t[ty + j * 8][tx] = W[(size_t)(k0 + ty + j * 8) * N + n0 + tx];
    __syncthreads();
    #pragma unroll
    for (int j = 0; j < 4; j++) {
        int n = n0 + ty + j * 8;
        float v = t[tx][ty + j * 8];
        bf16 h, l; split_hl(v, h, l);
        ThT[(size_t)n * K + k0 + tx] = h;
        TlT[(size_t)n * K + k0 + tx] = l;
    }
}

// batched: wq/wk/wv -> fused qkvT buffer (z=0..2), wo -> woT (z=3); all 1024x1024
__global__ __launch_bounds__(256)
void wconv_qkvo(const float* __restrict__ wq, const float* __restrict__ wk,
                const float* __restrict__ wv, const float* __restrict__ wo,
                bf16* __restrict__ qkvh, bf16* __restrict__ qkvl,
                bf16* __restrict__ woh, bf16* __restrict__ wol)
{
    const int z = blockIdx.z;
    const float* W = (z == 0) ? wq : (z == 1) ? wk : (z == 2) ? wv : wo;
    bf16* Th = (z < 3) ? qkvh + (size_t)z * DMODEL * DMODEL : woh;
    bf16* Tl = (z < 3) ? qkvl + (size_t)z * DMODEL * DMODEL : wol;

    __shared__ float t[32][33];
    int tx = threadIdx.x & 31, ty = threadIdx.x >> 5;
    int k0 = blockIdx.y * 32, n0 = blockIdx.x * 32;
    #pragma unroll
    for (int j = 0; j < 4; j++)
        t[ty + j * 8][tx] = W[(size_t)(k0 + ty + j * 8) * DMODEL + n0 + tx];
    __syncthreads();
    #pragma unroll
    for (int j = 0; j < 4; j++) {
        int n = n0 + ty + j * 8;
        float v = t[tx][ty + j * 8];
        bf16 h, l; split_hl(v, h, l);
        Th[(size_t)n * DMODEL + k0 + tx] = h;
        Tl[(size_t)n * DMODEL + k0 + tx] = l;
    }
}

// ---------------- mma.sync bf16x3 GEMM: C[M,N] = A[M,K] @ B^T (B given as [N,K]) --
// CTA 128x128, BK=64, 256 threads, warp grid 2(M)x4(N), warp tile 64x32.
// 3-stage cp.async, ONE barrier per chunk. CORRECT ordering:
//   wait(own chunk-i group) -> __syncthreads (publish all threads' chunk-i data;
//   also separates iter i-1 reads of stage (i-1)%3 from this iter's prefetch
//   writes into it) -> prefetch chunk i+2 -> compute chunk i from stage i%3.
// MMA pass-major: dependent MMAs on one acc are 16 apart.
// EPI: 2 = +bias,gelu -> hi/lo bf16; 3 = +bias +res -> fp32;
//      5 = fused QKV routing (seg0 Q*0.125, seg1 K tok-major; seg2 V head-transposed)
#define TILE_BYTES 16384
#define STAGE_BYTES (4*TILE_BYTES)
#define GEMM_SMEM   (3*STAGE_BYTES)      // 196608

template<int EPI>
__global__ __launch_bounds__(256, 1)
void gemm_mma(const bf16* __restrict__ Ahi, const bf16* __restrict__ Alo,
              const bf16* __restrict__ Bhi, const bf16* __restrict__ Blo,
              const float* __restrict__ bias, const float* __restrict__ res,
              float* __restrict__ Cf, bf16* __restrict__ Chi, bf16* __restrict__ Clo,
              int M, int N, int K)
{
    extern __shared__ char smem[];
    const uint32_t sbase = smem_u32(smem);
    const int tid  = threadIdx.x;
    const int wid  = tid >> 5, lane = tid & 31;
    const int m0 = blockIdx.y * 128, n0 = blockIdx.x * 128;
    const int wm = (wid & 1) * 64, wn = (wid >> 1) * 32;

    const bf16* srcs[4];
    srcs[0] = Ahi + (size_t)m0 * K;
    srcs[1] = Alo + (size_t)m0 * K;
    srcs[2] = Bhi + (size_t)n0 * K;
    srcs[3] = Blo + (size_t)n0 * K;

    float acc[4][4][4];
    #pragma unroll
    for (int a = 0; a < 4; a++)
        #pragma unroll
        for (int b = 0; b < 4; b++)
            #pragma unroll
            for (int c = 0; c < 4; c++) acc[a][b][c] = 0.f;

    const int NC = K >> 6;

    auto load_stage = [&](int chunk, int stage) {
        const int k0 = chunk << 6;
        const uint32_t base = sbase + stage * STAGE_BYTES;
        #pragma unroll
        for (int j = 0; j < 16; j++) {
            const int tile = j >> 2;
            const int cid  = ((j & 3) << 8) + tid;
            const int row  = cid >> 3;
            const int c    = cid & 7;
            uint32_t dst = base + tile * TILE_BYTES + row * 128 + ((c ^ (row & 7)) << 4);
            cpa16(dst, srcs[tile] + (size_t)row * K + k0 + c * 8);
        }
        cpa_commit();
    };

    load_stage(0, 0);
    load_stage(1, 1);

    for (int i = 0; i < NC; i++) {
        if (i + 1 < NC) cpa_wait1(); else cpa_wait0();   // own chunk-i group done
        __syncthreads();                                 // publish; fence prev reads
        if (i + 2 < NC) load_stage(i + 2, (i + 2) % 3);  // writes stage (i-1)%3: safe
        const uint32_t tb = sbase + (i % 3) * STAGE_BYTES;

        #pragma unroll
        for (int ks = 0; ks < 4; ks++) {
            uint32_t ah[4][4], al[4][4], bh[2][4], bl[2][4];
            #pragma unroll
            for (int mt = 0; mt < 4; mt++) {
                int row = wm + mt * 16 + (lane & 15);
                int kg  = ks * 2 + (lane >> 4);
                uint32_t off = row * 128 + ((kg ^ (row & 7)) << 4);
                LDSM4(ah[mt], tb + off);
                LDSM4(al[mt], tb + TILE_BYTES + off);
            }
            #pragma unroll
            for (int bt = 0; bt < 2; bt++) {
                int row = wn + bt * 16 + ((lane >> 4) << 3) + (lane & 7);
                int kg  = ks * 2 + ((lane >> 3) & 1);
                uint32_t off = row * 128 + ((kg ^ (row & 7)) << 4);
                LDSM4(bh[bt], tb + 2 * TILE_BYTES + off);
                LDSM4(bl[bt], tb + 3 * TILE_BYTES + off);
            }
            // pass-major: dependent MMAs on the same acc are 16 instructions apart
            #pragma unroll
            for (int mt = 0; mt < 4; mt++)
                #pragma unroll
                for (int nt = 0; nt < 4; nt++)
                    MMA_BF16(acc[mt][nt], ah[mt],
                             bh[nt >> 1][(nt & 1) * 2], bh[nt >> 1][(nt & 1) * 2 + 1]);
            #pragma unroll
            for (int mt = 0; mt < 4; mt++)
                #pragma unroll
                for (int nt = 0; nt < 4; nt++)
                    MMA_BF16(acc[mt][nt], ah[mt],
                             bl[nt >> 1][(nt & 1) * 2], bl[nt >> 1][(nt & 1) * 2 + 1]);
            #pragma unroll
            for (int mt = 0; mt < 4; mt++)
                #pragma unroll
                for (int nt = 0; nt < 4; nt++)
                    MMA_BF16(acc[mt][nt], al[mt],
                             bh[nt >> 1][(nt & 1) * 2], bh[nt >> 1][(nt & 1) * 2 + 1]);
        }
    }

    // ---- epilogue (fragment: rows g, g+8; cols 2t, 2t+1) ----
    const int g = lane >> 2, t = lane & 3;
    #pragma unroll
    for (int mt = 0; mt < 4; mt++) {
        #pragma unroll
        for (int nt = 0; nt < 4; nt++) {
            const int gr0 = m0 + wm + mt * 16 + g;
            const int gr1 = gr0 + 8;
            const int gc  = n0 + wn + nt * 8 + 2 * t;
            float v00 = acc[mt][nt][0], v01 = acc[mt][nt][1];
            float v10 = acc[mt][nt][2], v11 = acc[mt][nt][3];
            if (EPI == 3) {
                const float2 bv  = *(const float2*)&bias[gc];
                const float2 r0v = *(const float2*)&res[(size_t)gr0 * N + gc];
                const float2 r1v = *(const float2*)&res[(size_t)gr1 * N + gc];
                *(float2*)&Cf[(size_t)gr0 * N + gc] =
                    make_float2(v00 + bv.x + r0v.x, v01 + bv.y + r0v.y);
                *(float2*)&Cf[(size_t)gr1 * N + gc] =
                    make_float2(v10 + bv.x + r1v.x, v11 + bv.y + r1v.y);
            } else if (EPI == 2) {
                const float2 bv = *(const float2*)&bias[gc];
                float x00 = gelu_tanh(v00 + bv.x), x01 = gelu_tanh(v01 + bv.y);
                float x10 = gelu_tanh(v10 + bv.x), x11 = gelu_tanh(v11 + bv.y);
                __nv_bfloat162 h0, l0, h1, l1;
                split_hl(x00, h0.x, l0.x); split_hl(x01, h0.y, l0.y);
                split_hl(x10, h1.x, l1.x); split_hl(x11, h1.y, l1.y);
                *(__nv_bfloat162*)&Chi[(size_t)gr0 * N + gc] = h0;
                *(__nv_bfloat162*)&Clo[(size_t)gr0 * N + gc] = l0;
                *(__nv_bfloat162*)&Chi[(size_t)gr1 * N + gc] = h1;
                *(__nv_bfloat162*)&Clo[(size_t)gr1 * N + gc] = l1;
            } else { // EPI == 5: fused QKV
                const int seg = gc >> 10;       // constant per CTA
                const int col = gc & 1023;
                if (seg == 0) { v00 *= 0.125f; v01 *= 0.125f; v10 *= 0.125f; v11 *= 0.125f; }
                if (seg < 2) {
                    const size_t base = (size_t)seg * SEGSZ;
                    __nv_bfloat162 h0, l0, h1, l1;
                    split_hl(v00, h0.x, l0.x); split_hl(v01, h0.y, l0.y);
                    split_hl(v10, h1.x, l1.x); split_hl(v11, h1.y, l1.y);
                    *(__nv_bfloat162*)&Chi[base + (size_t)gr0 * DMODEL + col] = h0;
                    *(__nv_bfloat162*)&Clo[base + (size_t)gr0 * DMODEL + col] = l0;
                    *(__nv_bfloat162*)&Chi[base + (size_t)gr1 * DMODEL + col] = h1;
                    *(__nv_bfloat162*)&Clo[base + (size_t)gr1 * DMODEL + col] = l1;
                } else {    // V head-transposed: [b*16+h][d][s]
                    #pragma unroll
                    for (int e = 0; e < 4; e++) {
                        int gr = (e < 2) ? gr0 : gr1;
                        int cc = col + (e & 1);
                        float v = (e == 0) ? v00 : (e == 1) ? v01 : (e == 2) ? v10 : v11;
                        int b = gr >> 11, s = gr & 2047;
                        int h = cc >> 6, d = cc & 63;
                        size_t o = 2 * SEGSZ + ((size_t)((b * 16 + h) * 64 + d)) * 2048 + s;
                        bf16 hh, ll; split_hl(v, hh, ll);
                        Chi[o] = hh;
                        Clo[o] = ll;
                    }
                }
            }
        }
    }
}

// ---------------- mma.sync flash attention (bf16x3, causal) -> ctx hi/lo ----------
// CTA: 128 q-rows x one (b,h). 256 threads = 8 warps x 16 rows. KV tile = 64 keys.
// Q is pre-scaled by 1/8 at the QKV epilogue.
#define ATT_SMEM (32768 + 2*32768)

__global__ __launch_bounds__(256, 1)
void attn_mma(const bf16* __restrict__ qhi, const bf16* __restrict__ qlo,
              const bf16* __restrict__ khi, const bf16* __restrict__ klo,
              const bf16* __restrict__ vthi, const bf16* __restrict__ vtlo,
              bf16* __restrict__ chi, bf16* __restrict__ clo)
{
    extern __shared__ char smem[];
    const uint32_t sbase = smem_u32(smem);
    const int tid  = threadIdx.x;
    const int wid  = tid >> 5, lane = tid & 31;
    const int g = lane >> 2, t = lane & 3;
    const int bh = blockIdx.y;
    const int b = bh >> 4, h = bh & 15;
    const int m0 = (gridDim.x - 1 - blockIdx.x) * 128;   // longest blocks first
    const int nit = m0 / 64 + 2;

    // ---- load Q tile (128 rows, hi/lo) ----
    {
        const bf16* qs[2] = { qhi + ((size_t)(b * SEQ + m0)) * DMODEL + h * 64,
                              qlo + ((size_t)(b * SEQ + m0)) * DMODEL + h * 64 };
        #pragma unroll
        for (int tl = 0; tl < 2; tl++)
            #pragma unroll
            for (int j = 0; j < 4; j++) {
                int cid = j * 256 + tid;
                int row = cid >> 3, c = cid & 7;
                cpa16(sbase + tl * 16384 + row * 128 + ((c ^ (row & 7)) << 4),
                      qs[tl] + (size_t)row * DMODEL + c * 8);
            }
        cpa_commit();
    }

    auto load_kv = [&](int it, int stage) {
        const int n0 = it * 64;
        const uint32_t base = sbase + 32768 + stage * 32768;
        const bf16* ks_[2] = { khi + ((size_t)(b * SEQ + n0)) * DMODEL + h * 64,
                               klo + ((size_t)(b * SEQ + n0)) * DMODEL + h * 64 };
        const bf16* vs_[2] = { vthi + ((size_t)(bh * 64)) * 2048 + n0,
                               vtlo + ((size_t)(bh * 64)) * 2048 + n0 };
        #pragma unroll
        for (int tl = 0; tl < 2; tl++)
            #pragma unroll
            for (int j = 0; j < 2; j++) {
                int cid = j * 256 + tid;
                int row = cid >> 3, c = cid & 7;
                uint32_t sw = row * 128 + ((c ^ (row & 7)) << 4);
                cpa16(base + tl * 8192 + sw,         ks_[tl] + (size_t)row * DMODEL + c * 8);
                cpa16(base + 16384 + tl * 8192 + sw, vs_[tl] + (size_t)row * 2048 + c * 8);
            }
        cpa_commit();
    };

    load_kv(0, 0);
    load_kv(1, 1);

    // Q fragments (constant across iters)
    cpa_wait2();
    __syncthreads();
    uint32_t qh[4][4], ql[4][4];
    #pragma unroll
    for (int ks = 0; ks < 4; ks++) {
        int row = wid * 16 + (lane & 15);
        int kg  = ks * 2 + (lane >> 4);
        uint32_t off = row * 128 + ((kg ^ (row & 7)) << 4);
        LDSM4(qh[ks], sbase + off);
        LDSM4(ql[ks], sbase + 16384 + off);
    }

    float m[2] = { -INFINITY, -INFINITY };
    float l[2] = { 0.f, 0.f };
    float acc_o[8][4];
    #pragma unroll
    for (int i = 0; i < 8; i++)
        #pragma unroll
        for (int c = 0; c < 4; c++) acc_o[i][c] = 0.f;

    const int rowL64 = (wid & 3) * 16 + g;
    const int wdiag  = (wid < 4) ? (nit - 2) : (nit - 1);

    for (int it = 0; it < nit; it++) {
        const int rem = nit - 1 - it;
        if (rem >= 1) cpa_wait1(); else cpa_wait0();
        __syncthreads();
        const uint32_t kb = sbase + 32768 + (it & 1) * 32768;
        const uint32_t vb = kb + 16384;
        const bool active = !(wid < 4 && it == nit - 1);

        if (active) {
            const bool diag = (it == wdiag);

            // ---- S = Q K^T (bf16x3, pass-major) ----
            float s[8][4];
            #pragma unroll
            for (int i = 0; i < 8; i++)
                #pragma unroll
                for (int c = 0; c < 4; c++) s[i][c] = 0.f;

            #pragma unroll
            for (int ks = 0; ks < 4; ks++) {
                uint32_t kh[4][4], kl[4][4];
                #pragma unroll
                for (int bt = 0; bt < 4; bt++) {
                    int row = bt * 16 + ((lane >> 4) << 3) + (lane & 7);
                    int kg  = ks * 2 + ((lane >> 3) & 1);
                    uint32_t off = row * 128 + ((kg ^ (row & 7)) << 4);
                    LDSM4(kh[bt], kb + off);
                    LDSM4(kl[bt], kb + 8192 + off);
                }
                #pragma unroll
                for (int nt = 0; nt < 8; nt++)
                    MMA_BF16(s[nt], qh[ks],
                             kh[nt >> 1][(nt & 1) * 2], kh[nt >> 1][(nt & 1) * 2 + 1]);
                #pragma unroll
                for (int nt = 0; nt < 8; nt++)
                    MMA_BF16(s[nt], qh[ks],
                             kl[nt >> 1][(nt & 1) * 2], kl[nt >> 1][(nt & 1) * 2 + 1]);
                #pragma unroll
                for (int nt = 0; nt < 8; nt++)
                    MMA_BF16(s[nt], ql[ks],
                             kh[nt >> 1][(nt & 1) * 2], kh[nt >> 1][(nt & 1) * 2 + 1]);
            }

            // ---- causal mask + online softmax (Q pre-scaled) ----
            #pragma unroll
            for (int nt = 0; nt < 8; nt++) {
                #pragma unroll
                for (int c = 0; c < 4; c++) {
                    int colL = nt * 8 + 2 * t + (c & 1);
                    int rowL = rowL64 + ((c >> 1) << 3);
                    if (diag && colL > rowL) s[nt][c] = -INFINITY;
                }
            }
            float mx0 = -INFINITY, mx1 = -INFINITY;
            #pragma unroll
            for (int nt = 0; nt < 8; nt++) {
                mx0 = fmaxf(mx0, fmaxf(s[nt][0], s[nt][1]));
                mx1 = fmaxf(mx1, fmaxf(s[nt][2], s[nt][3]));
            }
            mx0 = fmaxf(mx0, __shfl_xor_sync(0xFFFFFFFFu, mx0, 1));
            mx0 = fmaxf(mx0, __shfl_xor_sync(0xFFFFFFFFu, mx0, 2));
            mx1 = fmaxf(mx1, __shfl_xor_sync(0xFFFFFFFFu, mx1, 1));
            mx1 = fmaxf(mx1, __shfl_xor_sync(0xFFFFFFFFu, mx1, 2));
            float mn0 = fmaxf(m[0], mx0), mn1 = fmaxf(m[1], mx1);
            float a0 = __expf(m[0] - mn0), a1 = __expf(m[1] - mn1);
            m[0] = mn0; m[1] = mn1;
            #pragma unroll
            for (int i = 0; i < 8; i++) {
                acc_o[i][0] *= a0; acc_o[i][1] *= a0;
                acc_o[i][2] *= a1; acc_o[i][3] *= a1;
            }
            float sum0 = 0.f, sum1 = 0.f;
            float p[8][4];
            #pragma unroll
            for (int nt = 0; nt < 8; nt++) {
                p[nt][0] = __expf(s[nt][0] - mn0); p[nt][1] = __expf(s[nt][1] - mn0);
                p[nt][2] = __expf(s[nt][2] - mn1); p[nt][3] = __expf(s[nt][3] - mn1);
                sum0 += p[nt][0] + p[nt][1];
                sum1 += p[nt][2] + p[nt][3];
            }
            sum0 += __shfl_xor_sync(0xFFFFFFFFu, sum0, 1);
            sum0 += __shfl_xor_sync(0xFFFFFFFFu, sum0, 2);
            sum1 += __shfl_xor_sync(0xFFFFFFFFu, sum1, 1);
            sum1 += __shfl_xor_sync(0xFFFFFFFFu, sum1, 2);
            l[0] = l[0] * a0 + sum0;
            l[1] = l[1] * a1 + sum1;

            // ---- O += P V (bf16x3, pass-major); P split hi/lo in-register ----
            #pragma unroll
            for (int ks2 = 0; ks2 < 4; ks2++) {
                float ph[8], pl[8];
                #pragma unroll
                for (int e = 0; e < 2; e++) {
                    int nt = 2 * ks2 + e;
                    #pragma unroll
                    for (int c = 0; c < 4; c++) {
                        bf16 hh, ll; split_hl(p[nt][c], hh, ll);
                        ph[e * 4 + c] = __bfloat162float(hh);
                        pl[e * 4 + c] = p[nt][c] - ph[e * 4 + c];
                    }
                }
                uint32_t pah[4], pal[4];
                pah[0] = pk2(ph[0], ph[1]); pah[1] = pk2(ph[2], ph[3]);
                pah[2] = pk2(ph[4], ph[5]); pah[3] = pk2(ph[6], ph[7]);
                pal[0] = pk2(pl[0], pl[1]); pal[1] = pk2(pl[2], pl[3]);
                pal[2] = pk2(pl[4], pl[5]); pal[3] = pk2(pl[6], pl[7]);

                uint32_t vh[4][4], vl[4][4];
                #pragma unroll
                for (int dt = 0; dt < 4; dt++) {
                    int row = dt * 16 + ((lane >> 4) << 3) + (lane & 7);
                    int kg  = ks2 * 2 + ((lane >> 3) & 1);
                    uint32_t off = row * 128 + ((kg ^ (row & 7)) << 4);
                    LDSM4(vh[dt], vb + off);
                    LDSM4(vl[dt], vb + 8192 + off);
                }
                #pragma unroll
                for (int nt = 0; nt < 8; nt++)
                    MMA_BF16(acc_o[nt], pah,
                             vh[nt >> 1][(nt & 1) * 2], vh[nt >> 1][(nt & 1) * 2 + 1]);
                #pragma unroll
                for (int nt = 0; nt < 8; nt++)
                    MMA_BF16(acc_o[nt], pah,
                             vl[nt >> 1][(nt & 1) * 2], vl[nt >> 1][(nt & 1) * 2 + 1]);
                #pragma unroll
                for (int nt = 0; nt < 8; nt++)
                    MMA_BF16(acc_o[nt], pal,
                             vh[nt >> 1][(nt & 1) * 2], vh[nt >> 1][(nt & 1) * 2 + 1]);
            }
        }

        __syncthreads();
        if (it + 2 < nit) load_kv(it + 2, it & 1);
    }

    // ---- epilogue ----
    float inv0 = 1.0f / l[0], inv1 = 1.0f / l[1];
    const size_t gr0 = (size_t)(b * SEQ + m0 + wid * 16 + g) * DMODEL + h * 64;
    const size_t gr1 = gr0 + 8 * DMODEL;
    #pragma unroll
    for (int nt = 0; nt < 8; nt++) {
        int gc = nt * 8 + 2 * t;
        __nv_bfloat162 h0, l0h, h1, l1h;
        split_hl(acc_o[nt][0] * inv0, h0.x, l0h.x);
        split_hl(acc_o[nt][1] * inv0, h0.y, l0h.y);
        split_hl(acc_o[nt][2] * inv1, h1.x, l1h.x);
        split_hl(acc_o[nt][3] * inv1, h1.y, l1h.y);
        *(__nv_bfloat162*)&chi[gr0 + gc] = h0;
        *(__nv_bfloat162*)&clo[gr0 + gc] = l0h;
        *(__nv_bfloat162*)&chi[gr1 + gc] = h1;
        *(__nv_bfloat162*)&clo[gr1 + gc] = l1h;
    }
}

// ---------------- launch ----------------
extern "C" void kernel_launch(void* const* d_in, const int* in_sizes, int n_in,
                              void* d_out, int out_size)
{
    const float* x         = (const float*)d_in[0];
    const float* ln1_scale = (const float*)d_in[1];
    const float* ln1_shift = (const float*)d_in[2];
    const float* wq        = (const float*)d_in[3];
    const float* wk        = (const float*)d_in[4];
    const float* wv        = (const float*)d_in[5];
    const float* w_out     = (const float*)d_in[6];
    const float* b_out     = (const float*)d_in[7];
    const float* ln2_scale = (const float*)d_in[8];
    const float* ln2_shift = (const float*)d_in[9];
    const float* w1        = (const float*)d_in[10];
    const float* b1        = (const float*)d_in[11];
    const float* w2        = (const float*)d_in[12];
    const float* b2        = (const float*)d_in[13];
    float* out = (float*)d_out;

    float *p_res1;
    bf16 *p_ln1h, *p_ln1l, *p_qkvh, *p_qkvl;
    bf16 *p_ctxh, *p_ctxl, *p_ln2h, *p_ln2l, *p_h1h, *p_h1l;
    bf16 *p_wqkvh, *p_wqkvl, *p_woh, *p_wol, *p_w1h, *p_w1l, *p_w2h, *p_w2l;
    cudaGetSymbolAddress((void**)&p_res1,  g_res1);
    cudaGetSymbolAddress((void**)&p_ln1h,  g_ln1_hi);
    cudaGetSymbolAddress((void**)&p_ln1l,  g_ln1_lo);
    cudaGetSymbolAddress((void**)&p_qkvh,  g_qkv_hi);
    cudaGetSymbolAddress((void**)&p_qkvl,  g_qkv_lo);
    cudaGetSymbolAddress((void**)&p_ctxh,  g_ctx_hi);
    cudaGetSymbolAddress((void**)&p_ctxl,  g_ctx_lo);
    cudaGetSymbolAddress((void**)&p_ln2h,  g_ln2_hi);
    cudaGetSymbolAddress((void**)&p_ln2l,  g_ln2_lo);
    cudaGetSymbolAddress((void**)&p_h1h,   g_h1_hi);
    cudaGetSymbolAddress((void**)&p_h1l,   g_h1_lo);
    cudaGetSymbolAddress((void**)&p_wqkvh, g_wqkvT_hi);
    cudaGetSymbolAddress((void**)&p_wqkvl, g_wqkvT_lo);
    cudaGetSymbolAddress((void**)&p_woh,   g_woT_hi);
    cudaGetSymbolAddress((void**)&p_wol,   g_woT_lo);
    cudaGetSymbolAddress((void**)&p_w1h,   g_w1T_hi);
    cudaGetSymbolAddress((void**)&p_w1l,   g_w1T_lo);
    cudaGetSymbolAddress((void**)&p_w2h,   g_w2T_hi);
    cudaGetSymbolAddress((void**)&p_w2l,   g_w2T_lo);

    static bool attr_set = false;
    if (!attr_set) {
        cudaFuncSetAttribute(attn_mma,    cudaFuncAttributeMaxDynamicSharedMemorySize, ATT_SMEM);
        cudaFuncSetAttribute(gemm_mma<2>, cudaFuncAttributeMaxDynamicSharedMemorySize, GEMM_SMEM);
        cudaFuncSetAttribute(gemm_mma<3>, cudaFuncAttributeMaxDynamicSharedMemorySize, GEMM_SMEM);
        cudaFuncSetAttribute(gemm_mma<5>, cudaFuncAttributeMaxDynamicSharedMemorySize, GEMM_SMEM);
        attr_set = true;
    }

    // 0) weight transpose + hi/lo convert
    wconv_qkvo<<<dim3(DMODEL/32, DMODEL/32, 4), 256>>>(wq, wk, wv, w_out,
                                                       p_wqkvh, p_wqkvl, p_woh, p_wol);
    wconvT<<<dim3(FFN/32,    DMODEL/32), 256>>>(w1, p_w1h, p_w1l, DMODEL, FFN);
    wconvT<<<dim3(DMODEL/32, FFN/32),    256>>>(w2, p_w2h, p_w2l, FFN,    DMODEL);

    // 1) LN1 -> hi/lo
    ln_hl_kernel<<<MTOK, 256>>>(x, ln1_scale, ln1_shift, p_ln1h, p_ln1l);

    dim3 gQKV(3*DMODEL/128, MTOK/128);
    dim3 g1024(DMODEL/128,  MTOK/128);
    dim3 g4096(FFN/128,     MTOK/128);

    // 2) fused QKV projection -> hi/lo bf16 (Q pre-scaled 1/8; V head-transposed)
    gemm_mma<5><<<gQKV, 256, GEMM_SMEM>>>(p_ln1h, p_ln1l, p_wqkvh, p_wqkvl,
                                          nullptr, nullptr, nullptr, p_qkvh, p_qkvl,
                                          MTOK, 3*DMODEL, DMODEL);

    // 3) attention (tensor core) -> ctx hi/lo
    dim3 gAttn(SEQ/128, BATCH*NHEAD);
    attn_mma<<<gAttn, 256, ATT_SMEM>>>(p_qkvh,            p_qkvl,
                                       p_qkvh + SEGSZ,    p_qkvl + SEGSZ,
                                       p_qkvh + 2*SEGSZ,  p_qkvl + 2*SEGSZ,
                                       p_ctxh, p_ctxl);

    // 4) out projection + bias + residual(x) -> res1 (fp32)
    gemm_mma<3><<<g1024, 256, GEMM_SMEM>>>(p_ctxh, p_ctxl, p_woh, p_wol,
                                           b_out, x, p_res1, nullptr, nullptr,
                                           MTOK, DMODEL, DMODEL);

    // 5) LN2 -> hi/lo
    ln_hl_kernel<<<MTOK, 256>>>(p_res1, ln2_scale, ln2_shift, p_ln2h, p_ln2l);

    // 6) FFN1 + bias + gelu -> h1 hi/lo
    gemm_mma<2><<<g4096, 256, GEMM_SMEM>>>(p_ln2h, p_ln2l, p_w1h, p_w1l,
                                           b1, nullptr, nullptr, p_h1h, p_h1l,
                                           MTOK, FFN, DMODEL);

    // 7) FFN2 + bias + residual(res1) -> out
    gemm_mma<3><<<g1024, 256, GEMM_SMEM>>>(p_h1h, p_h1l, p_w2h, p_w2l,
                                           b2, p_res1, out, nullptr, nullptr,
                                           MTOK, DMODEL, FFN);

    (void)in_sizes; (void)n_in; (void)out_size;
}